// round 14
// baseline (speedup 1.0000x reference)
#include <cuda_runtime.h>
#include <cuda_fp16.h>
#include <math.h>
#include <stdint.h>

// GPT-2 small config
#define BATCH 4
#define TLEN  1024
#define EMB   768
#define NLAYER 12
#define VOCAB 50257
#define NHEAD 12
#define HEADD 64
#define MROW  (BATCH * TLEN)   // 4096

// ---------------- scratch (device globals; no allocation allowed) ----------------
__device__ float g_x[MROW * EMB];        // residual stream (fp32)

// fp16 activations
__device__ __half g_h[MROW * EMB];
__device__ __half g_qkv16[MROW * 3 * EMB];
__device__ __half g_y[MROW * EMB];
__device__ __half g_f1[MROW * 4 * EMB];

// fp16 weights, stored [N][K] (K-major rows) for ldmatrix col access
__device__ __half g_wqkv[NLAYER * 3 * EMB * EMB];
__device__ __half g_wproj[NLAYER * EMB * EMB];
__device__ __half g_wf1[NLAYER * 4 * EMB * EMB];
__device__ __half g_wf2[NLAYER * 4 * EMB * EMB];
__device__ __half g_wte16[VOCAB * EMB];

// ======================= helpers =======================
__device__ __forceinline__ uint32_t smem_u32(const void* p) {
    uint32_t a;
    asm("{ .reg .u64 t; cvta.to.shared.u64 t, %1; cvt.u32.u64 %0, t; }"
        : "=r"(a) : "l"(p));
    return a;
}
__device__ __forceinline__ void ldsm_x4(uint32_t addr, uint32_t* r) {
    asm volatile("ldmatrix.sync.aligned.m8n8.x4.shared.b16 {%0,%1,%2,%3}, [%4];"
                 : "=r"(r[0]), "=r"(r[1]), "=r"(r[2]), "=r"(r[3]) : "r"(addr));
}
__device__ __forceinline__ void ldsm_x2(uint32_t addr, uint32_t* r) {
    asm volatile("ldmatrix.sync.aligned.m8n8.x2.shared.b16 {%0,%1}, [%2];"
                 : "=r"(r[0]), "=r"(r[1]) : "r"(addr));
}
__device__ __forceinline__ void ldsm_x2t(uint32_t addr, uint32_t* r) {
    asm volatile("ldmatrix.sync.aligned.m8n8.x2.trans.shared.b16 {%0,%1}, [%2];"
                 : "=r"(r[0]), "=r"(r[1]) : "r"(addr));
}
__device__ __forceinline__ void mma_fp16(float* d, const uint32_t* a, const uint32_t* b) {
    asm volatile(
        "mma.sync.aligned.m16n8k16.row.col.f32.f16.f16.f32 "
        "{%0,%1,%2,%3}, {%4,%5,%6,%7}, {%8,%9}, {%0,%1,%2,%3};"
        : "+f"(d[0]), "+f"(d[1]), "+f"(d[2]), "+f"(d[3])
        : "r"(a[0]), "r"(a[1]), "r"(a[2]), "r"(a[3]), "r"(b[0]), "r"(b[1]));
}
__device__ __forceinline__ void cp16(uint32_t saddr, const void* g) {
    asm volatile("cp.async.cg.shared.global [%0], [%1], 16;" :: "r"(saddr), "l"(g));
}
__device__ __forceinline__ void cp16z(uint32_t saddr, const void* g, int ok) {
    int sz = ok ? 16 : 0;
    asm volatile("cp.async.cg.shared.global [%0], [%1], 16, %2;" :: "r"(saddr), "l"(g), "r"(sz));
}
#define CP_COMMIT() asm volatile("cp.async.commit_group;" ::: "memory")
#define CP_WAIT1()  asm volatile("cp.async.wait_group 1;" ::: "memory")

__device__ __forceinline__ uint32_t packh2(float a, float b) {
    __half2 t = __floats2half2_rn(a, b);
    return reinterpret_cast<uint32_t&>(t);
}
__device__ __forceinline__ float gelu_f(float x) {
    return 0.5f * x * (1.0f + erff(x * 0.7071067811865476f));
}

// ======================= weight convert kernels =======================
__global__ void cvt_kernel(const float* __restrict__ src,
                           __half* __restrict__ dst, int n4) {
    int i = blockIdx.x * blockDim.x + threadIdx.x;
    if (i >= n4) return;
    float4 v = ((const float4*)src)[i];
    uint2 o;
    o.x = packh2(v.x, v.y);
    o.y = packh2(v.z, v.w);
    ((uint2*)dst)[i] = o;
}

__global__ void __launch_bounds__(256) cvtT2_kernel(
    const float* __restrict__ srcA, __half* __restrict__ dstA, int KA, int NA,
    const float* __restrict__ srcB, __half* __restrict__ dstB, int KB, int NB) {
    __shared__ float t[32][33];
    int z = blockIdx.z;
    const float* src;  __half* dst;  int K, N;
    if (z < NLAYER) {
        src = srcA + (size_t)z * KA * NA;  dst = dstA + (size_t)z * KA * NA;
        K = KA;  N = NA;
    } else {
        src = srcB + (size_t)(z - NLAYER) * KB * NB;  dst = dstB + (size_t)(z - NLAYER) * KB * NB;
        K = KB;  N = NB;
    }
    int bn = blockIdx.x * 32, bk = blockIdx.y * 32;
    if (bn >= N || bk >= K) return;
    int tx = threadIdx.x & 31, ty = threadIdx.x >> 5;
#pragma unroll
    for (int i = 0; i < 4; i++)
        t[ty + i * 8][tx] = src[(size_t)(bk + ty + i * 8) * N + bn + tx];
    __syncthreads();
#pragma unroll
    for (int i = 0; i < 4; i++) {
        int n = bn + ty + i * 8;
        int k = bk + tx;
        dst[(size_t)n * K + k] = __float2half_rn(t[tx][ty + i * 8]);
    }
}

// ======================= mma.sync fp16 GEMM (256 threads / CTA) =======================
// CTA tile 128x128, 8 warps (32x64 warp tile), K-chunk 32, double buffer.
// EPI: 0=none(fp32 C), 1=+bias(fp32), 2=+bias+residual(fp32),
//      3=+bias,GELU->fp16, 5=+bias->fp16
// RAGGED: guard B rows / C cols against N (lm_head)
#define TCSTRIDE 80
#define REG_B    10240                    // A region bytes (128*80)
#define STAGE_BYTES 20480                 // + B region
#define GEMM_SMEM (2 * STAGE_BYTES)

template <int EPI, int RAGGED>
__global__ void __launch_bounds__(256) tc_gemm(const __half* __restrict__ A,
                                               const __half* __restrict__ B,
                                               const float* __restrict__ bias,
                                               const float* __restrict__ R,
                                               float* __restrict__ C,
                                               __half* __restrict__ Ch,
                                               int N, int K) {
    extern __shared__ char sm[];
    const uint32_t sbase = smem_u32(sm);
    const int tid = threadIdx.x;
    const int warp = tid >> 5, lane = tid & 31;

    // m-inner ordering: consecutive CTAs share the same B tile (L2 reuse)
    const int m0 = (blockIdx.x & 31) * 128;
    const int n0 = (blockIdx.x >> 5) * 128;

    const int warpM = (warp >> 1) * 32;   // 4 m-strips of 32 rows
    const int warpN = (warp & 1) * 64;    // 2 n-strips of 64 cols

    float acc[2][8][4];
#pragma unroll
    for (int i = 0; i < 2; i++)
#pragma unroll
        for (int j = 0; j < 8; j++)
#pragma unroll
            for (int c = 0; c < 4; c++) acc[i][j][c] = 0.f;

    const int NK = K >> 5;

    // fill: A 512 chunks + B 512 chunks over 256 threads -> 2+2 cp.async each
    auto fill = [&](int s) {
        const uint32_t st = sbase + (s & 1) * STAGE_BYTES;
        const int k0 = s << 5;
#pragma unroll
        for (int u = 0; u < 2; u++) {
            int id = tid + (u << 8);
            int row = id >> 2, c = id & 3;
            cp16(st + row * TCSTRIDE + c * 16,
                 A + (size_t)(m0 + row) * K + k0 + c * 8);
        }
#pragma unroll
        for (int u = 0; u < 2; u++) {
            int id = tid + (u << 8);
            int row = id >> 2, c = id & 3;
            uint32_t so = st + REG_B + row * TCSTRIDE + c * 16;
            int gn = n0 + row;
            if (RAGGED) {
                int ok = gn < N;
                int gnc = ok ? gn : 0;
                cp16z(so, B + (size_t)gnc * K + k0 + c * 8, ok);
            } else {
                cp16(so, B + (size_t)gn * K + k0 + c * 8);
            }
        }
    };

    fill(0); CP_COMMIT();
    fill(1); CP_COMMIT();

    const uint32_t aoff = (uint32_t)((warpM + (lane & 15)) * TCSTRIDE + ((lane >> 4) * 8) * 2);
    const uint32_t boff = (uint32_t)((warpN + (lane & 7)) * TCSTRIDE + (((lane >> 3) & 1) * 8) * 2);

    for (int kt = 0; kt < NK; kt++) {
        CP_WAIT1();
        __syncthreads();
        const uint32_t st = sbase + (kt & 1) * STAGE_BYTES;

#pragma unroll
        for (int ks = 0; ks < 2; ks++) {
            uint32_t af[2][4];
#pragma unroll
            for (int mt = 0; mt < 2; mt++)
                ldsm_x4(st + aoff + mt * (16 * TCSTRIDE) + (ks * 32), af[mt]);
#pragma unroll
            for (int nh = 0; nh < 2; nh++) {
                uint32_t bf[4][2];
#pragma unroll
                for (int j = 0; j < 4; j++)
                    ldsm_x2(st + REG_B + boff + (nh * 4 + j) * (8 * TCSTRIDE) + (ks * 32), bf[j]);
#pragma unroll
                for (int mt = 0; mt < 2; mt++)
#pragma unroll
                    for (int j = 0; j < 4; j++)
                        mma_fp16(acc[mt][nh * 4 + j], af[mt], bf[j]);
            }
        }
        __syncthreads();
        if (kt + 2 < NK) fill(kt + 2);
        CP_COMMIT();
    }

    // ---- epilogue ----
    const int g = lane >> 2, t4 = lane & 3;
#pragma unroll
    for (int mt = 0; mt < 2; mt++) {
#pragma unroll
        for (int nt = 0; nt < 8; nt++) {
            int col = n0 + warpN + nt * 8 + 2 * t4;
            int row0 = m0 + warpM + mt * 16 + g;
#pragma unroll
            for (int h = 0; h < 2; h++) {
                int rowg = row0 + h * 8;
                float v0 = acc[mt][nt][2 * h];
                float v1 = acc[mt][nt][2 * h + 1];
                if (RAGGED) {
                    if (col < N) {
                        if (EPI >= 1) v0 += bias[col];
                        C[(size_t)rowg * N + col] = v0;
                    }
                    if (col + 1 < N) {
                        if (EPI >= 1) v1 += bias[col + 1];
                        C[(size_t)rowg * N + col + 1] = v1;
                    }
                } else if (EPI == 3 || EPI == 5) {
                    v0 += bias[col]; v1 += bias[col + 1];
                    if (EPI == 3) { v0 = gelu_f(v0); v1 = gelu_f(v1); }
                    *(__half2*)&Ch[(size_t)rowg * N + col] = __floats2half2_rn(v0, v1);
                } else {
                    if (EPI >= 1) { v0 += bias[col]; v1 += bias[col + 1]; }
                    if (EPI == 2) {
                        v0 += R[(size_t)rowg * N + col];
                        v1 += R[(size_t)rowg * N + col + 1];
                    }
                    float2 o = make_float2(v0, v1);
                    *(float2*)&C[(size_t)rowg * N + col] = o;
                }
            }
        }
    }
}

// ---------------- embedding: x = wte[idx] + wpe[t] ----------------
__global__ void embed_kernel(const int* __restrict__ idx,
                             const float* __restrict__ wte,
                             const float* __restrict__ wpe,
                             float* __restrict__ x) {
    int i = blockIdx.x * blockDim.x + threadIdx.x;
    if (i >= MROW * EMB) return;
    int row = i / EMB;
    int e = i - row * EMB;
    int t = row % TLEN;
    x[i] = wte[(size_t)idx[row] * EMB + e] + wpe[(size_t)t * EMB + e];
}

// ---------------- layernorm: fp32 in, fp16 out ----------------
__global__ void __launch_bounds__(256) ln_kernel(const float* __restrict__ x,
                                                 const float* __restrict__ w,
                                                 const float* __restrict__ b,
                                                 __half* __restrict__ o16) {
    __shared__ float red[8];
    __shared__ float s_mean, s_var;
    int row = blockIdx.x;
    int tid = threadIdx.x;
    int warp = tid >> 5, lane = tid & 31;
    const float* xr = x + (size_t)row * EMB;

    float v0 = xr[tid], v1 = xr[tid + 256], v2 = xr[tid + 512];
    float s = v0 + v1 + v2;
#pragma unroll
    for (int o = 16; o; o >>= 1) s += __shfl_xor_sync(0xffffffffu, s, o);
    if (lane == 0) red[warp] = s;
    __syncthreads();
    if (tid == 0) {
        float t = 0.f;
#pragma unroll
        for (int i = 0; i < 8; i++) t += red[i];
        s_mean = t * (1.0f / EMB);
    }
    __syncthreads();
    float m = s_mean;
    float d0 = v0 - m, d1 = v1 - m, d2 = v2 - m;
    float q = d0 * d0 + d1 * d1 + d2 * d2;
#pragma unroll
    for (int o = 16; o; o >>= 1) q += __shfl_xor_sync(0xffffffffu, q, o);
    if (lane == 0) red[warp] = q;
    __syncthreads();
    if (tid == 0) {
        float t = 0.f;
#pragma unroll
        for (int i = 0; i < 8; i++) t += red[i];
        s_var = t * (1.0f / EMB);
    }
    __syncthreads();
    float r = rsqrtf(s_var + 1e-5f);
    size_t base = (size_t)row * EMB;
#pragma unroll
    for (int u = 0; u < 3; u++) {
        int e = tid + u * 256;
        float d = (u == 0 ? d0 : (u == 1 ? d1 : d2));
        o16[base + e] = __float2half_rn(d * r * w[e] + b[e]);
    }
}

// ---------------- flash attention: tensor cores, 64q x 64k tiles ----------------
#define ASTR 144

__global__ void __launch_bounds__(128) fattn_kernel(const __half* __restrict__ qkv,
                                                    __half* __restrict__ y) {
    __shared__ __align__(16) char smem[3 * 64 * ASTR];
    const uint32_t sQ = smem_u32(smem);
    const uint32_t sK = sQ + 64 * ASTR;
    const uint32_t sV = sK + 64 * ASTR;
    const int tid = threadIdx.x, warp = tid >> 5, lane = tid & 31;
    const int g = lane >> 2, t4 = lane & 3;
    const int bh = blockIdx.x;
    const int b = bh / NHEAD, h = bh % NHEAD;
    const int qb = blockIdx.y;
    const size_t row0g = (size_t)(b * TLEN);

#pragma unroll
    for (int u = 0; u < 4; u++) {
        int id = tid + u * 128;
        int row = id >> 3, c = id & 7;
        const uint4* src = (const uint4*)(qkv + (row0g + qb * 64 + row) * (3 * EMB) + h * HEADD + c * 8);
        *(uint4*)(smem + row * ASTR + c * 16) = *src;
    }
    __syncthreads();

    uint32_t qf[4][4];
    {
        uint32_t aoffQ = sQ + (warp * 16 + (lane & 15)) * ASTR + ((lane >> 4) * 16);
#pragma unroll
        for (int ks = 0; ks < 4; ks++) ldsm_x4(aoffQ + ks * 32, qf[ks]);
    }

    float m0 = -1e30f, m1 = -1e30f, l0 = 0.f, l1 = 0.f;
    float O[8][4];
#pragma unroll
    for (int j = 0; j < 8; j++)
#pragma unroll
        for (int e = 0; e < 4; e++) O[j][e] = 0.f;

    const uint32_t boffK = sK + (lane & 7) * ASTR + ((lane >> 3) & 1) * 16;
    const uint32_t boffV = sV + ((lane & 7) + ((lane >> 3) & 1) * 8) * ASTR;

    for (int c = 0; c <= qb; c++) {
        __syncthreads();
#pragma unroll
        for (int u = 0; u < 4; u++) {
            int id = tid + u * 128;
            int row = id >> 3, cc = id & 7;
            const __half* src = qkv + (row0g + c * 64 + row) * (3 * EMB) + EMB + h * HEADD + cc * 8;
            *(uint4*)(smem + 64 * ASTR + row * ASTR + cc * 16) = *(const uint4*)src;
            *(uint4*)(smem + 128 * ASTR + row * ASTR + cc * 16) = *(const uint4*)(src + EMB);
        }
        __syncthreads();

        float S[8][4];
#pragma unroll
        for (int j = 0; j < 8; j++)
#pragma unroll
            for (int e = 0; e < 4; e++) S[j][e] = 0.f;
#pragma unroll
        for (int ks = 0; ks < 4; ks++) {
#pragma unroll
            for (int j = 0; j < 8; j++) {
                uint32_t bf[2];
                ldsm_x2(boffK + j * (8 * ASTR) + ks * 32, bf);
                mma_fp16(S[j], qf[ks], bf);
            }
        }
#pragma unroll
        for (int j = 0; j < 8; j++)
#pragma unroll
            for (int e = 0; e < 4; e++) S[j][e] *= 0.125f;
        if (c == qb) {
            int q0l = warp * 16 + g, q1l = q0l + 8;
#pragma unroll
            for (int j = 0; j < 8; j++) {
                int k0 = j * 8 + 2 * t4;
                if (k0 > q0l)     S[j][0] = -1e30f;
                if (k0 + 1 > q0l) S[j][1] = -1e30f;
                if (k0 > q1l)     S[j][2] = -1e30f;
                if (k0 + 1 > q1l) S[j][3] = -1e30f;
            }
        }
        float rm0 = -1e30f, rm1 = -1e30f;
#pragma unroll
        for (int j = 0; j < 8; j++) {
            rm0 = fmaxf(rm0, fmaxf(S[j][0], S[j][1]));
            rm1 = fmaxf(rm1, fmaxf(S[j][2], S[j][3]));
        }
        rm0 = fmaxf(rm0, __shfl_xor_sync(0xffffffffu, rm0, 1));
        rm0 = fmaxf(rm0, __shfl_xor_sync(0xffffffffu, rm0, 2));
        rm1 = fmaxf(rm1, __shfl_xor_sync(0xffffffffu, rm1, 1));
        rm1 = fmaxf(rm1, __shfl_xor_sync(0xffffffffu, rm1, 2));
        float mn0 = fmaxf(m0, rm0), mn1 = fmaxf(m1, rm1);
        float corr0 = __expf(m0 - mn0), corr1 = __expf(m1 - mn1);
        m0 = mn0; m1 = mn1;
        float rs0 = 0.f, rs1 = 0.f;
#pragma unroll
        for (int j = 0; j < 8; j++) {
            S[j][0] = __expf(S[j][0] - mn0);
            S[j][1] = __expf(S[j][1] - mn0);
            S[j][2] = __expf(S[j][2] - mn1);
            S[j][3] = __expf(S[j][3] - mn1);
            rs0 += S[j][0] + S[j][1];
            rs1 += S[j][2] + S[j][3];
        }
        rs0 += __shfl_xor_sync(0xffffffffu, rs0, 1);
        rs0 += __shfl_xor_sync(0xffffffffu, rs0, 2);
        rs1 += __shfl_xor_sync(0xffffffffu, rs1, 1);
        rs1 += __shfl_xor_sync(0xffffffffu, rs1, 2);
        l0 = l0 * corr0 + rs0;
        l1 = l1 * corr1 + rs1;
#pragma unroll
        for (int j = 0; j < 8; j++) {
            O[j][0] *= corr0; O[j][1] *= corr0;
            O[j][2] *= corr1; O[j][3] *= corr1;
        }
#pragma unroll
        for (int kc = 0; kc < 4; kc++) {
            uint32_t pa[4];
            pa[0] = packh2(S[2 * kc][0],     S[2 * kc][1]);
            pa[1] = packh2(S[2 * kc][2],     S[2 * kc][3]);
            pa[2] = packh2(S[2 * kc + 1][0], S[2 * kc + 1][1]);
            pa[3] = packh2(S[2 * kc + 1][2], S[2 * kc + 1][3]);
#pragma unroll
            for (int jd = 0; jd < 8; jd++) {
                uint32_t bv[2];
                ldsm_x2t(boffV + kc * (16 * ASTR) + jd * 16, bv);
                mma_fp16(O[jd], pa, bv);
            }
        }
    }

    float i0 = 1.0f / l0, i1 = 1.0f / l1;
    int qrow = qb * 64 + warp * 16 + g;
    size_t ybase = (row0g + qrow) * EMB + h * HEADD;
#pragma unroll
    for (int jd = 0; jd < 8; jd++) {
        int col = jd * 8 + 2 * t4;
        *(__half2*)&y[ybase + col] = __floats2half2_rn(O[jd][0] * i0, O[jd][1] * i0);
        *(__half2*)&y[ybase + 8 * EMB + col] = __floats2half2_rn(O[jd][2] * i1, O[jd][3] * i1);
    }
}

// ---------------- host launch ----------------
extern "C" void kernel_launch(void* const* d_in, const int* in_sizes, int n_in,
                              void* d_out, int out_size) {
    (void)in_sizes; (void)n_in; (void)out_size;
    const int*   x_idx  = (const int*)d_in[0];
    const float* wte    = (const float*)d_in[1];
    const float* wpe    = (const float*)d_in[2];
    const float* ln1_w  = (const float*)d_in[3];
    const float* ln1_b  = (const float*)d_in[4];
    const float* attn_w = (const float*)d_in[5];
    const float* attn_b = (const float*)d_in[6];
    const float* proj_w = (const float*)d_in[7];
    const float* proj_b = (const float*)d_in[8];
    const float* ln2_w  = (const float*)d_in[9];
    const float* ln2_b  = (const float*)d_in[10];
    const float* fc1_w  = (const float*)d_in[11];
    const float* fc1_b  = (const float*)d_in[12];
    const float* fc2_w  = (const float*)d_in[13];
    const float* fc2_b  = (const float*)d_in[14];
    const float* lnf_w  = (const float*)d_in[15];
    const float* lnf_b  = (const float*)d_in[16];
    float* out = (float*)d_out;

    float *gx;
    __half *gh, *gqkv, *gy, *gf1;
    __half *wq, *wp, *w1, *w2, *wt;
    cudaGetSymbolAddress((void**)&gx,   g_x);
    cudaGetSymbolAddress((void**)&gh,   g_h);
    cudaGetSymbolAddress((void**)&gqkv, g_qkv16);
    cudaGetSymbolAddress((void**)&gy,   g_y);
    cudaGetSymbolAddress((void**)&gf1,  g_f1);
    cudaGetSymbolAddress((void**)&wq,   g_wqkv);
    cudaGetSymbolAddress((void**)&wp,   g_wproj);
    cudaGetSymbolAddress((void**)&w1,   g_wf1);
    cudaGetSymbolAddress((void**)&w2,   g_wf2);
    cudaGetSymbolAddress((void**)&wt,   g_wte16);

    cudaFuncSetAttribute(tc_gemm<5, 0>, cudaFuncAttributeMaxDynamicSharedMemorySize, GEMM_SMEM);
    cudaFuncSetAttribute(tc_gemm<2, 0>, cudaFuncAttributeMaxDynamicSharedMemorySize, GEMM_SMEM);
    cudaFuncSetAttribute(tc_gemm<3, 0>, cudaFuncAttributeMaxDynamicSharedMemorySize, GEMM_SMEM);
    cudaFuncSetAttribute(tc_gemm<0, 1>, cudaFuncAttributeMaxDynamicSharedMemorySize, GEMM_SMEM);

    // launch order keeps the first qkv GEMM at launch #6 for ncu (-s 5 -c 1)
    embed_kernel<<<(MROW * EMB + 255) / 256, 256>>>(x_idx, wte, wpe, gx);          // 1
    cvtT2_kernel<<<dim3(96, 24, 2 * NLAYER), 256>>>(                               // 2
        attn_w, wq, EMB, 3 * EMB, fc1_w, w1, EMB, 4 * EMB);
    cvtT2_kernel<<<dim3(24, 96, 2 * NLAYER), 256>>>(                               // 3
        proj_w, wp, EMB, EMB, fc2_w, w2, 4 * EMB, EMB);
    cvt_kernel<<<(VOCAB * EMB / 4 + 255) / 256, 256>>>(wte, wt, VOCAB * EMB / 4);  // 4

    for (int l = 0; l < NLAYER; l++) {
        ln_kernel<<<MROW, 256>>>(gx, ln1_w + (size_t)l * EMB, ln1_b + (size_t)l * EMB, gh);  // 5

        // qkv = h @ attn_w + attn_b -> fp16  (N=2304)                             // 6 <- ncu
        tc_gemm<5, 0><<<32 * 18, 256, GEMM_SMEM>>>(
            gh, wq + (size_t)l * 3 * EMB * EMB,
            attn_b + (size_t)l * 3 * EMB, nullptr, nullptr, gqkv, 3 * EMB, EMB);

        fattn_kernel<<<dim3(BATCH * NHEAD, TLEN / 64), 128>>>(gqkv, gy);

        // x = x + y @ proj_w + proj_b  (N=768)
        tc_gemm<2, 0><<<32 * 6, 256, GEMM_SMEM>>>(
            gy, wp + (size_t)l * EMB * EMB,
            proj_b + (size_t)l * EMB, gx, gx, nullptr, EMB, EMB);

        ln_kernel<<<MROW, 256>>>(gx, ln2_w + (size_t)l * EMB, ln2_b + (size_t)l * EMB, gh);

        // f1 = gelu(h @ fc1_w + fc1_b) -> fp16  (N=3072)
        tc_gemm<3, 0><<<32 * 24, 256, GEMM_SMEM>>>(
            gh, w1 + (size_t)l * 4 * EMB * EMB,
            fc1_b + (size_t)l * 4 * EMB, nullptr, nullptr, gf1, 4 * EMB, EMB);

        // x = x + f1 @ fc2_w + fc2_b   (N=768, K=3072)
        tc_gemm<2, 0><<<32 * 6, 256, GEMM_SMEM>>>(
            gf1, w2 + (size_t)l * 4 * EMB * EMB,
            fc2_b + (size_t)l * EMB, gx, gx, nullptr, EMB, 4 * EMB);
    }

    ln_kernel<<<MROW, 256>>>(gx, lnf_w, lnf_b, gh);

    // logits = h @ wte^T  (N=50257, ragged)
    tc_gemm<0, 1><<<32 * 393, 256, GEMM_SMEM>>>(
        gh, wt, nullptr, nullptr, out, nullptr, VOCAB, EMB);
}

// round 15
// speedup vs baseline: 1.2230x; 1.2230x over previous
#include <cuda_runtime.h>
#include <cuda_fp16.h>
#include <math.h>
#include <stdint.h>

// GPT-2 small config
#define BATCH 4
#define TLEN  1024
#define EMB   768
#define NLAYER 12
#define VOCAB 50257
#define NHEAD 12
#define HEADD 64
#define MROW  (BATCH * TLEN)   // 4096

// ---------------- scratch (device globals; no allocation allowed) ----------------
__device__ float g_x[MROW * EMB];        // residual stream (fp32)

// fp16 activations
__device__ __half g_h[MROW * EMB];
__device__ __half g_qkv16[MROW * 3 * EMB];
__device__ __half g_y[MROW * EMB];
__device__ __half g_f1[MROW * 4 * EMB];

// fp16 weights, stored [N][K] (K-major rows) for ldmatrix col access
__device__ __half g_wqkv[NLAYER * 3 * EMB * EMB];
__device__ __half g_wproj[NLAYER * EMB * EMB];
__device__ __half g_wf1[NLAYER * 4 * EMB * EMB];
__device__ __half g_wf2[NLAYER * 4 * EMB * EMB];
__device__ __half g_wte16[VOCAB * EMB];

// ======================= helpers =======================
__device__ __forceinline__ uint32_t smem_u32(const void* p) {
    uint32_t a;
    asm("{ .reg .u64 t; cvta.to.shared.u64 t, %1; cvt.u32.u64 %0, t; }"
        : "=r"(a) : "l"(p));
    return a;
}
__device__ __forceinline__ void ldsm_x4(uint32_t addr, uint32_t* r) {
    asm volatile("ldmatrix.sync.aligned.m8n8.x4.shared.b16 {%0,%1,%2,%3}, [%4];"
                 : "=r"(r[0]), "=r"(r[1]), "=r"(r[2]), "=r"(r[3]) : "r"(addr));
}
__device__ __forceinline__ void ldsm_x2(uint32_t addr, uint32_t* r) {
    asm volatile("ldmatrix.sync.aligned.m8n8.x2.shared.b16 {%0,%1}, [%2];"
                 : "=r"(r[0]), "=r"(r[1]) : "r"(addr));
}
__device__ __forceinline__ void ldsm_x2t(uint32_t addr, uint32_t* r) {
    asm volatile("ldmatrix.sync.aligned.m8n8.x2.trans.shared.b16 {%0,%1}, [%2];"
                 : "=r"(r[0]), "=r"(r[1]) : "r"(addr));
}
__device__ __forceinline__ void mma_fp16(float* d, const uint32_t* a, const uint32_t* b) {
    asm volatile(
        "mma.sync.aligned.m16n8k16.row.col.f32.f16.f16.f32 "
        "{%0,%1,%2,%3}, {%4,%5,%6,%7}, {%8,%9}, {%0,%1,%2,%3};"
        : "+f"(d[0]), "+f"(d[1]), "+f"(d[2]), "+f"(d[3])
        : "r"(a[0]), "r"(a[1]), "r"(a[2]), "r"(a[3]), "r"(b[0]), "r"(b[1]));
}
__device__ __forceinline__ void cp16(uint32_t saddr, const void* g) {
    asm volatile("cp.async.cg.shared.global [%0], [%1], 16;" :: "r"(saddr), "l"(g));
}
__device__ __forceinline__ void cp16z(uint32_t saddr, const void* g, int ok) {
    int sz = ok ? 16 : 0;
    asm volatile("cp.async.cg.shared.global [%0], [%1], 16, %2;" :: "r"(saddr), "l"(g), "r"(sz));
}
#define CP_COMMIT() asm volatile("cp.async.commit_group;" ::: "memory")
#define CP_WAIT1()  asm volatile("cp.async.wait_group 1;" ::: "memory")

__device__ __forceinline__ uint32_t packh2(float a, float b) {
    __half2 t = __floats2half2_rn(a, b);
    return reinterpret_cast<uint32_t&>(t);
}
__device__ __forceinline__ float gelu_f(float x) {
    return 0.5f * x * (1.0f + erff(x * 0.7071067811865476f));
}
// XOR-swizzled smem address: 64B rows, 4x16B slots, conflict-free for
// both ldmatrix 8-row phases and cp.async 8-thread store phases.
__device__ __forceinline__ uint32_t swz64(int row, int c) {
    return (uint32_t)(row * 64 + ((c ^ ((row >> 1) & 3)) << 4));
}

// ======================= weight convert kernels =======================
__global__ void cvt_kernel(const float* __restrict__ src,
                           __half* __restrict__ dst, int n4) {
    int i = blockIdx.x * blockDim.x + threadIdx.x;
    if (i >= n4) return;
    float4 v = ((const float4*)src)[i];
    uint2 o;
    o.x = packh2(v.x, v.y);
    o.y = packh2(v.z, v.w);
    ((uint2*)dst)[i] = o;
}

__global__ void __launch_bounds__(256) cvtT2_kernel(
    const float* __restrict__ srcA, __half* __restrict__ dstA, int KA, int NA,
    const float* __restrict__ srcB, __half* __restrict__ dstB, int KB, int NB) {
    __shared__ float t[32][33];
    int z = blockIdx.z;
    const float* src;  __half* dst;  int K, N;
    if (z < NLAYER) {
        src = srcA + (size_t)z * KA * NA;  dst = dstA + (size_t)z * KA * NA;
        K = KA;  N = NA;
    } else {
        src = srcB + (size_t)(z - NLAYER) * KB * NB;  dst = dstB + (size_t)(z - NLAYER) * KB * NB;
        K = KB;  N = NB;
    }
    int bn = blockIdx.x * 32, bk = blockIdx.y * 32;
    if (bn >= N || bk >= K) return;
    int tx = threadIdx.x & 31, ty = threadIdx.x >> 5;
#pragma unroll
    for (int i = 0; i < 4; i++)
        t[ty + i * 8][tx] = src[(size_t)(bk + ty + i * 8) * N + bn + tx];
    __syncthreads();
#pragma unroll
    for (int i = 0; i < 4; i++) {
        int n = bn + ty + i * 8;
        int k = bk + tx;
        dst[(size_t)n * K + k] = __float2half_rn(t[tx][ty + i * 8]);
    }
}

// ======================= mma.sync fp16 GEMM (swizzled smem) =======================
// 128 threads, 4 warps. MT=4: 128x128 tile (64x64 warp tile); MT=2: 64x128 tile.
// K-chunk 32, double buffer, XOR-swizzled 64B-row smem, B loaded via ldsm_x4.
// EPI: 0=none(fp32 C), 1=+bias(fp32), 2=+bias+residual(fp32),
//      3=+bias,GELU->fp16, 5=+bias->fp16
// RAGGED: guard B rows / C cols against N (lm_head)
template <int EPI, int RAGGED, int MT>
__global__ void __launch_bounds__(128) tc_gemm(const __half* __restrict__ A,
                                               const __half* __restrict__ B,
                                               const float* __restrict__ bias,
                                               const float* __restrict__ R,
                                               float* __restrict__ C,
                                               __half* __restrict__ Ch,
                                               int N, int K) {
    constexpr int TILE_M = MT * 32;
    constexpr int REG_B = TILE_M * 64;            // A region bytes
    constexpr int STAGE = REG_B + 128 * 64;       // + B region
    constexpr int MTILES = MROW / TILE_M;

    extern __shared__ char sm[];
    const uint32_t sbase = smem_u32(sm);
    const int tid = threadIdx.x;
    const int warp = tid >> 5, lane = tid & 31;

    // m-inner ordering: consecutive CTAs share the same B tile (L2 reuse)
    const int m0 = (blockIdx.x % MTILES) * TILE_M;
    const int n0 = (blockIdx.x / MTILES) * 128;

    const int warpM = (warp >> 1) * (TILE_M / 2);
    const int warpN = (warp & 1) * 64;

    float acc[MT][8][4];
#pragma unroll
    for (int i = 0; i < MT; i++)
#pragma unroll
        for (int j = 0; j < 8; j++)
#pragma unroll
            for (int c = 0; c < 4; c++) acc[i][j][c] = 0.f;

    const int NK = K >> 5;

    auto fill = [&](int s) {
        const uint32_t st = sbase + (s & 1) * STAGE;
        const int k0 = s << 5;
#pragma unroll
        for (int u = 0; u < MT; u++) {
            int id = tid + (u << 7);
            int row = id >> 2, c = id & 3;
            cp16(st + swz64(row, c), A + (size_t)(m0 + row) * K + k0 + c * 8);
        }
#pragma unroll
        for (int u = 0; u < 4; u++) {
            int id = tid + (u << 7);
            int row = id >> 2, c = id & 3;
            uint32_t so = st + REG_B + swz64(row, c);
            int gn = n0 + row;
            if (RAGGED) {
                int ok = gn < N;
                int gnc = ok ? gn : 0;
                cp16z(so, B + (size_t)gnc * K + k0 + c * 8, ok);
            } else {
                cp16(so, B + (size_t)gn * K + k0 + c * 8);
            }
        }
    };

    fill(0); CP_COMMIT();
    fill(1); CP_COMMIT();

    // per-lane fragment address components (swizzled)
    const int ar = warpM + (lane & 15);
    const uint32_t abase = (uint32_t)(ar * 64);
    const int axr = (ar >> 1) & 3;                 // invariant across +16-row mt steps
    const int ahalf = lane >> 4;                   // 16B half within 32B k-step

    const int br = warpN + (lane & 7) + ((lane >> 4) << 3);
    const uint32_t bbase = (uint32_t)(REG_B + br * 64);
    const int bxr = (br >> 1) & 3;
    const int bhalf = (lane >> 3) & 1;

    for (int kt = 0; kt < NK; kt++) {
        CP_WAIT1();
        __syncthreads();
        const uint32_t st = sbase + (kt & 1) * STAGE;

#pragma unroll
        for (int ks = 0; ks < 2; ks++) {
            uint32_t af[MT][4];
#pragma unroll
            for (int mt = 0; mt < MT; mt++)
                ldsm_x4(st + abase + mt * 1024 + (((ks * 2 + ahalf) ^ axr) << 4), af[mt]);
#pragma unroll
            for (int nh = 0; nh < 2; nh++) {
                uint32_t bf4[2][4];   // [j2][2 n8-groups x 2 k-halves]
#pragma unroll
                for (int j2 = 0; j2 < 2; j2++)
                    ldsm_x4(st + bbase + (nh * 2 + j2) * 1024 +
                            (((ks * 2 + bhalf) ^ bxr) << 4), bf4[j2]);
#pragma unroll
                for (int mt = 0; mt < MT; mt++)
#pragma unroll
                    for (int j = 0; j < 4; j++)
                        mma_fp16(acc[mt][nh * 4 + j], af[mt], &bf4[j >> 1][(j & 1) * 2]);
            }
        }
        __syncthreads();
        if (kt + 2 < NK) fill(kt + 2);
        CP_COMMIT();
    }

    // ---- epilogue ----
    const int g = lane >> 2, t4 = lane & 3;
#pragma unroll
    for (int mt = 0; mt < MT; mt++) {
#pragma unroll
        for (int nt = 0; nt < 8; nt++) {
            int col = n0 + warpN + nt * 8 + 2 * t4;
            int row0 = m0 + warpM + mt * 16 + g;
#pragma unroll
            for (int h = 0; h < 2; h++) {
                int rowg = row0 + h * 8;
                float v0 = acc[mt][nt][2 * h];
                float v1 = acc[mt][nt][2 * h + 1];
                if (RAGGED) {
                    if (col < N) {
                        if (EPI >= 1) v0 += bias[col];
                        C[(size_t)rowg * N + col] = v0;
                    }
                    if (col + 1 < N) {
                        if (EPI >= 1) v1 += bias[col + 1];
                        C[(size_t)rowg * N + col + 1] = v1;
                    }
                } else if (EPI == 3 || EPI == 5) {
                    v0 += bias[col]; v1 += bias[col + 1];
                    if (EPI == 3) { v0 = gelu_f(v0); v1 = gelu_f(v1); }
                    *(__half2*)&Ch[(size_t)rowg * N + col] = __floats2half2_rn(v0, v1);
                } else {
                    if (EPI >= 1) { v0 += bias[col]; v1 += bias[col + 1]; }
                    if (EPI == 2) {
                        v0 += R[(size_t)rowg * N + col];
                        v1 += R[(size_t)rowg * N + col + 1];
                    }
                    float2 o = make_float2(v0, v1);
                    *(float2*)&C[(size_t)rowg * N + col] = o;
                }
            }
        }
    }
}

#define SMEM_MT4 (2 * (128 * 64 + 128 * 64))   // 32768
#define SMEM_MT2 (2 * (64 * 64 + 128 * 64))    // 24576

// ---------------- embedding: x = wte[idx] + wpe[t] ----------------
__global__ void embed_kernel(const int* __restrict__ idx,
                             const float* __restrict__ wte,
                             const float* __restrict__ wpe,
                             float* __restrict__ x) {
    int i = blockIdx.x * blockDim.x + threadIdx.x;
    if (i >= MROW * EMB) return;
    int row = i / EMB;
    int e = i - row * EMB;
    int t = row % TLEN;
    x[i] = wte[(size_t)idx[row] * EMB + e] + wpe[(size_t)t * EMB + e];
}

// ---------------- layernorm: fp32 in, fp16 out ----------------
__global__ void __launch_bounds__(256) ln_kernel(const float* __restrict__ x,
                                                 const float* __restrict__ w,
                                                 const float* __restrict__ b,
                                                 __half* __restrict__ o16) {
    __shared__ float red[8];
    __shared__ float s_mean, s_var;
    int row = blockIdx.x;
    int tid = threadIdx.x;
    int warp = tid >> 5, lane = tid & 31;
    const float* xr = x + (size_t)row * EMB;

    float v0 = xr[tid], v1 = xr[tid + 256], v2 = xr[tid + 512];
    float s = v0 + v1 + v2;
#pragma unroll
    for (int o = 16; o; o >>= 1) s += __shfl_xor_sync(0xffffffffu, s, o);
    if (lane == 0) red[warp] = s;
    __syncthreads();
    if (tid == 0) {
        float t = 0.f;
#pragma unroll
        for (int i = 0; i < 8; i++) t += red[i];
        s_mean = t * (1.0f / EMB);
    }
    __syncthreads();
    float m = s_mean;
    float d0 = v0 - m, d1 = v1 - m, d2 = v2 - m;
    float q = d0 * d0 + d1 * d1 + d2 * d2;
#pragma unroll
    for (int o = 16; o; o >>= 1) q += __shfl_xor_sync(0xffffffffu, q, o);
    if (lane == 0) red[warp] = q;
    __syncthreads();
    if (tid == 0) {
        float t = 0.f;
#pragma unroll
        for (int i = 0; i < 8; i++) t += red[i];
        s_var = t * (1.0f / EMB);
    }
    __syncthreads();
    float r = rsqrtf(s_var + 1e-5f);
    size_t base = (size_t)row * EMB;
#pragma unroll
    for (int u = 0; u < 3; u++) {
        int e = tid + u * 256;
        float d = (u == 0 ? d0 : (u == 1 ? d1 : d2));
        o16[base + e] = __float2half_rn(d * r * w[e] + b[e]);
    }
}

// ---------------- flash attention: tensor cores, 64q x 64k tiles ----------------
#define ASTR 144

__global__ void __launch_bounds__(128) fattn_kernel(const __half* __restrict__ qkv,
                                                    __half* __restrict__ y) {
    __shared__ __align__(16) char smem[3 * 64 * ASTR];
    const uint32_t sQ = smem_u32(smem);
    const uint32_t sK = sQ + 64 * ASTR;
    const uint32_t sV = sK + 64 * ASTR;
    const int tid = threadIdx.x, warp = tid >> 5, lane = tid & 31;
    const int g = lane >> 2, t4 = lane & 3;
    const int bh = blockIdx.x;
    const int b = bh / NHEAD, h = bh % NHEAD;
    const int qb = blockIdx.y;
    const size_t row0g = (size_t)(b * TLEN);

#pragma unroll
    for (int u = 0; u < 4; u++) {
        int id = tid + u * 128;
        int row = id >> 3, c = id & 7;
        const uint4* src = (const uint4*)(qkv + (row0g + qb * 64 + row) * (3 * EMB) + h * HEADD + c * 8);
        *(uint4*)(smem + row * ASTR + c * 16) = *src;
    }
    __syncthreads();

    uint32_t qf[4][4];
    {
        uint32_t aoffQ = sQ + (warp * 16 + (lane & 15)) * ASTR + ((lane >> 4) * 16);
#pragma unroll
        for (int ks = 0; ks < 4; ks++) ldsm_x4(aoffQ + ks * 32, qf[ks]);
    }

    float m0 = -1e30f, m1 = -1e30f, l0 = 0.f, l1 = 0.f;
    float O[8][4];
#pragma unroll
    for (int j = 0; j < 8; j++)
#pragma unroll
        for (int e = 0; e < 4; e++) O[j][e] = 0.f;

    const uint32_t boffK = sK + (lane & 7) * ASTR + ((lane >> 3) & 1) * 16;
    const uint32_t boffV = sV + ((lane & 7) + ((lane >> 3) & 1) * 8) * ASTR;

    for (int c = 0; c <= qb; c++) {
        __syncthreads();
#pragma unroll
        for (int u = 0; u < 4; u++) {
            int id = tid + u * 128;
            int row = id >> 3, cc = id & 7;
            const __half* src = qkv + (row0g + c * 64 + row) * (3 * EMB) + EMB + h * HEADD + cc * 8;
            *(uint4*)(smem + 64 * ASTR + row * ASTR + cc * 16) = *(const uint4*)src;
            *(uint4*)(smem + 128 * ASTR + row * ASTR + cc * 16) = *(const uint4*)(src + EMB);
        }
        __syncthreads();

        float S[8][4];
#pragma unroll
        for (int j = 0; j < 8; j++)
#pragma unroll
            for (int e = 0; e < 4; e++) S[j][e] = 0.f;
#pragma unroll
        for (int ks = 0; ks < 4; ks++) {
#pragma unroll
            for (int j = 0; j < 8; j++) {
                uint32_t bf[2];
                ldsm_x2(boffK + j * (8 * ASTR) + ks * 32, bf);
                mma_fp16(S[j], qf[ks], bf);
            }
        }
#pragma unroll
        for (int j = 0; j < 8; j++)
#pragma unroll
            for (int e = 0; e < 4; e++) S[j][e] *= 0.125f;
        if (c == qb) {
            int q0l = warp * 16 + g, q1l = q0l + 8;
#pragma unroll
            for (int j = 0; j < 8; j++) {
                int k0 = j * 8 + 2 * t4;
                if (k0 > q0l)     S[j][0] = -1e30f;
                if (k0 + 1 > q0l) S[j][1] = -1e30f;
                if (k0 > q1l)     S[j][2] = -1e30f;
                if (k0 + 1 > q1l) S[j][3] = -1e30f;
            }
        }
        float rm0 = -1e30f, rm1 = -1e30f;
#pragma unroll
        for (int j = 0; j < 8; j++) {
            rm0 = fmaxf(rm0, fmaxf(S[j][0], S[j][1]));
            rm1 = fmaxf(rm1, fmaxf(S[j][2], S[j][3]));
        }
        rm0 = fmaxf(rm0, __shfl_xor_sync(0xffffffffu, rm0, 1));
        rm0 = fmaxf(rm0, __shfl_xor_sync(0xffffffffu, rm0, 2));
        rm1 = fmaxf(rm1, __shfl_xor_sync(0xffffffffu, rm1, 1));
        rm1 = fmaxf(rm1, __shfl_xor_sync(0xffffffffu, rm1, 2));
        float mn0 = fmaxf(m0, rm0), mn1 = fmaxf(m1, rm1);
        float corr0 = __expf(m0 - mn0), corr1 = __expf(m1 - mn1);
        m0 = mn0; m1 = mn1;
        float rs0 = 0.f, rs1 = 0.f;
#pragma unroll
        for (int j = 0; j < 8; j++) {
            S[j][0] = __expf(S[j][0] - mn0);
            S[j][1] = __expf(S[j][1] - mn0);
            S[j][2] = __expf(S[j][2] - mn1);
            S[j][3] = __expf(S[j][3] - mn1);
            rs0 += S[j][0] + S[j][1];
            rs1 += S[j][2] + S[j][3];
        }
        rs0 += __shfl_xor_sync(0xffffffffu, rs0, 1);
        rs0 += __shfl_xor_sync(0xffffffffu, rs0, 2);
        rs1 += __shfl_xor_sync(0xffffffffu, rs1, 1);
        rs1 += __shfl_xor_sync(0xffffffffu, rs1, 2);
        l0 = l0 * corr0 + rs0;
        l1 = l1 * corr1 + rs1;
#pragma unroll
        for (int j = 0; j < 8; j++) {
            O[j][0] *= corr0; O[j][1] *= corr0;
            O[j][2] *= corr1; O[j][3] *= corr1;
        }
#pragma unroll
        for (int kc = 0; kc < 4; kc++) {
            uint32_t pa[4];
            pa[0] = packh2(S[2 * kc][0],     S[2 * kc][1]);
            pa[1] = packh2(S[2 * kc][2],     S[2 * kc][3]);
            pa[2] = packh2(S[2 * kc + 1][0], S[2 * kc + 1][1]);
            pa[3] = packh2(S[2 * kc + 1][2], S[2 * kc + 1][3]);
#pragma unroll
            for (int jd = 0; jd < 8; jd++) {
                uint32_t bv[2];
                ldsm_x2t(boffV + kc * (16 * ASTR) + jd * 16, bv);
                mma_fp16(O[jd], pa, bv);
            }
        }
    }

    float i0 = 1.0f / l0, i1 = 1.0f / l1;
    int qrow = qb * 64 + warp * 16 + g;
    size_t ybase = (row0g + qrow) * EMB + h * HEADD;
#pragma unroll
    for (int jd = 0; jd < 8; jd++) {
        int col = jd * 8 + 2 * t4;
        *(__half2*)&y[ybase + col] = __floats2half2_rn(O[jd][0] * i0, O[jd][1] * i0);
        *(__half2*)&y[ybase + 8 * EMB + col] = __floats2half2_rn(O[jd][2] * i1, O[jd][3] * i1);
    }
}

// ---------------- host launch ----------------
extern "C" void kernel_launch(void* const* d_in, const int* in_sizes, int n_in,
                              void* d_out, int out_size) {
    (void)in_sizes; (void)n_in; (void)out_size;
    const int*   x_idx  = (const int*)d_in[0];
    const float* wte    = (const float*)d_in[1];
    const float* wpe    = (const float*)d_in[2];
    const float* ln1_w  = (const float*)d_in[3];
    const float* ln1_b  = (const float*)d_in[4];
    const float* attn_w = (const float*)d_in[5];
    const float* attn_b = (const float*)d_in[6];
    const float* proj_w = (const float*)d_in[7];
    const float* proj_b = (const float*)d_in[8];
    const float* ln2_w  = (const float*)d_in[9];
    const float* ln2_b  = (const float*)d_in[10];
    const float* fc1_w  = (const float*)d_in[11];
    const float* fc1_b  = (const float*)d_in[12];
    const float* fc2_w  = (const float*)d_in[13];
    const float* fc2_b  = (const float*)d_in[14];
    const float* lnf_w  = (const float*)d_in[15];
    const float* lnf_b  = (const float*)d_in[16];
    float* out = (float*)d_out;

    float *gx;
    __half *gh, *gqkv, *gy, *gf1;
    __half *wq, *wp, *w1, *w2, *wt;
    cudaGetSymbolAddress((void**)&gx,   g_x);
    cudaGetSymbolAddress((void**)&gh,   g_h);
    cudaGetSymbolAddress((void**)&gqkv, g_qkv16);
    cudaGetSymbolAddress((void**)&gy,   g_y);
    cudaGetSymbolAddress((void**)&gf1,  g_f1);
    cudaGetSymbolAddress((void**)&wq,   g_wqkv);
    cudaGetSymbolAddress((void**)&wp,   g_wproj);
    cudaGetSymbolAddress((void**)&w1,   g_wf1);
    cudaGetSymbolAddress((void**)&w2,   g_wf2);
    cudaGetSymbolAddress((void**)&wt,   g_wte16);

    cudaFuncSetAttribute(tc_gemm<5, 0, 4>, cudaFuncAttributeMaxDynamicSharedMemorySize, SMEM_MT4);
    cudaFuncSetAttribute(tc_gemm<2, 0, 2>, cudaFuncAttributeMaxDynamicSharedMemorySize, SMEM_MT2);
    cudaFuncSetAttribute(tc_gemm<3, 0, 4>, cudaFuncAttributeMaxDynamicSharedMemorySize, SMEM_MT4);
    cudaFuncSetAttribute(tc_gemm<0, 1, 4>, cudaFuncAttributeMaxDynamicSharedMemorySize, SMEM_MT4);

    // launch order keeps the first qkv GEMM at launch #6 for ncu (-s 5 -c 1)
    embed_kernel<<<(MROW * EMB + 255) / 256, 256>>>(x_idx, wte, wpe, gx);          // 1
    cvtT2_kernel<<<dim3(96, 24, 2 * NLAYER), 256>>>(                               // 2
        attn_w, wq, EMB, 3 * EMB, fc1_w, w1, EMB, 4 * EMB);
    cvtT2_kernel<<<dim3(24, 96, 2 * NLAYER), 256>>>(                               // 3
        proj_w, wp, EMB, EMB, fc2_w, w2, 4 * EMB, EMB);
    cvt_kernel<<<(VOCAB * EMB / 4 + 255) / 256, 256>>>(wte, wt, VOCAB * EMB / 4);  // 4

    for (int l = 0; l < NLAYER; l++) {
        ln_kernel<<<MROW, 256>>>(gx, ln1_w + (size_t)l * EMB, ln1_b + (size_t)l * EMB, gh);  // 5

        // qkv = h @ attn_w + attn_b -> fp16  (N=2304, 128x128 tiles)              // 6 <- ncu
        tc_gemm<5, 0, 4><<<32 * 18, 128, SMEM_MT4>>>(
            gh, wq + (size_t)l * 3 * EMB * EMB,
            attn_b + (size_t)l * 3 * EMB, nullptr, nullptr, gqkv, 3 * EMB, EMB);

        fattn_kernel<<<dim3(BATCH * NHEAD, TLEN / 64), 128>>>(gqkv, gy);

        // x = x + y @ proj_w + proj_b  (N=768, 64x128 tiles -> 384 CTAs)
        tc_gemm<2, 0, 2><<<64 * 6, 128, SMEM_MT2>>>(
            gy, wp + (size_t)l * EMB * EMB,
            proj_b + (size_t)l * EMB, gx, gx, nullptr, EMB, EMB);

        ln_kernel<<<MROW, 256>>>(gx, ln2_w + (size_t)l * EMB, ln2_b + (size_t)l * EMB, gh);

        // f1 = gelu(h @ fc1_w + fc1_b) -> fp16  (N=3072, 128x128 tiles)
        tc_gemm<3, 0, 4><<<32 * 24, 128, SMEM_MT4>>>(
            gh, w1 + (size_t)l * 4 * EMB * EMB,
            fc1_b + (size_t)l * 4 * EMB, nullptr, nullptr, gf1, 4 * EMB, EMB);

        // x = x + f1 @ fc2_w + fc2_b   (N=768, K=3072, 64x128 tiles -> 384 CTAs)
        tc_gemm<2, 0, 2><<<64 * 6, 128, SMEM_MT2>>>(
            gf1, w2 + (size_t)l * 4 * EMB * EMB,
            fc2_b + (size_t)l * EMB, gx, gx, nullptr, EMB, 4 * EMB);
    }

    ln_kernel<<<MROW, 256>>>(gx, lnf_w, lnf_b, gh);

    // logits = h @ wte^T  (N=50257, 128x128 tiles, ragged)
    tc_gemm<0, 1, 4><<<32 * 393, 128, SMEM_MT4>>>(
        gh, wt, nullptr, nullptr, out, nullptr, VOCAB, EMB);
}

// round 16
// speedup vs baseline: 1.3237x; 1.0824x over previous
#include <cuda_runtime.h>
#include <cuda_fp16.h>
#include <math.h>
#include <stdint.h>

// GPT-2 small config
#define BATCH 4
#define TLEN  1024
#define EMB   768
#define NLAYER 12
#define VOCAB 50257
#define NHEAD 12
#define HEADD 64
#define MROW  (BATCH * TLEN)   // 4096

// ---------------- scratch (device globals; no allocation allowed) ----------------
__device__ float g_x[MROW * EMB];        // residual stream (fp32)

// fp16 activations
__device__ __half g_h[MROW * EMB];
__device__ __half g_qkv16[MROW * 3 * EMB];
__device__ __half g_y[MROW * EMB];
__device__ __half g_f1[MROW * 4 * EMB];

// fp16 weights, stored [N][K] (K-major rows) for ldmatrix col access
__device__ __half g_wqkv[NLAYER * 3 * EMB * EMB];
__device__ __half g_wproj[NLAYER * EMB * EMB];
__device__ __half g_wf1[NLAYER * 4 * EMB * EMB];
__device__ __half g_wf2[NLAYER * 4 * EMB * EMB];
__device__ __half g_wte16[VOCAB * EMB];

// ======================= helpers =======================
__device__ __forceinline__ uint32_t smem_u32(const void* p) {
    uint32_t a;
    asm("{ .reg .u64 t; cvta.to.shared.u64 t, %1; cvt.u32.u64 %0, t; }"
        : "=r"(a) : "l"(p));
    return a;
}
__device__ __forceinline__ void ldsm_x4(uint32_t addr, uint32_t* r) {
    asm volatile("ldmatrix.sync.aligned.m8n8.x4.shared.b16 {%0,%1,%2,%3}, [%4];"
                 : "=r"(r[0]), "=r"(r[1]), "=r"(r[2]), "=r"(r[3]) : "r"(addr));
}
__device__ __forceinline__ void ldsm_x2(uint32_t addr, uint32_t* r) {
    asm volatile("ldmatrix.sync.aligned.m8n8.x2.shared.b16 {%0,%1}, [%2];"
                 : "=r"(r[0]), "=r"(r[1]) : "r"(addr));
}
__device__ __forceinline__ void ldsm_x2t(uint32_t addr, uint32_t* r) {
    asm volatile("ldmatrix.sync.aligned.m8n8.x2.trans.shared.b16 {%0,%1}, [%2];"
                 : "=r"(r[0]), "=r"(r[1]) : "r"(addr));
}
__device__ __forceinline__ void mma_fp16(float* d, const uint32_t* a, const uint32_t* b) {
    asm volatile(
        "mma.sync.aligned.m16n8k16.row.col.f32.f16.f16.f32 "
        "{%0,%1,%2,%3}, {%4,%5,%6,%7}, {%8,%9}, {%0,%1,%2,%3};"
        : "+f"(d[0]), "+f"(d[1]), "+f"(d[2]), "+f"(d[3])
        : "r"(a[0]), "r"(a[1]), "r"(a[2]), "r"(a[3]), "r"(b[0]), "r"(b[1]));
}
__device__ __forceinline__ void cp16(uint32_t saddr, const void* g) {
    asm volatile("cp.async.cg.shared.global [%0], [%1], 16;" :: "r"(saddr), "l"(g));
}
__device__ __forceinline__ void cp16z(uint32_t saddr, const void* g, int ok) {
    int sz = ok ? 16 : 0;
    asm volatile("cp.async.cg.shared.global [%0], [%1], 16, %2;" :: "r"(saddr), "l"(g), "r"(sz));
}
#define CP_COMMIT() asm volatile("cp.async.commit_group;" ::: "memory")
#define CP_WAIT2()  asm volatile("cp.async.wait_group 2;" ::: "memory")

__device__ __forceinline__ uint32_t packh2(float a, float b) {
    __half2 t = __floats2half2_rn(a, b);
    return reinterpret_cast<uint32_t&>(t);
}
__device__ __forceinline__ float gelu_f(float x) {
    return 0.5f * x * (1.0f + erff(x * 0.7071067811865476f));
}
// XOR-swizzled smem address: 64B rows, 4x16B slots, conflict-free for
// both ldmatrix 8-row phases and cp.async 8-thread store phases.
__device__ __forceinline__ uint32_t swz64(int row, int c) {
    return (uint32_t)(row * 64 + ((c ^ ((row >> 1) & 3)) << 4));
}

// ======================= weight convert kernels =======================
__global__ void cvt_kernel(const float* __restrict__ src,
                           __half* __restrict__ dst, int n4) {
    int i = blockIdx.x * blockDim.x + threadIdx.x;
    if (i >= n4) return;
    float4 v = ((const float4*)src)[i];
    uint2 o;
    o.x = packh2(v.x, v.y);
    o.y = packh2(v.z, v.w);
    ((uint2*)dst)[i] = o;
}

// transpose+convert for TWO weight families; 32n x 64k tiles, half2 stores.
__global__ void __launch_bounds__(256) cvtT2_kernel(
    const float* __restrict__ srcA, __half* __restrict__ dstA, int KA, int NA,
    const float* __restrict__ srcB, __half* __restrict__ dstB, int KB, int NB) {
    __shared__ float t[64][33];
    int z = blockIdx.z;
    const float* src;  __half* dst;  int K, N;
    if (z < NLAYER) {
        src = srcA + (size_t)z * KA * NA;  dst = dstA + (size_t)z * KA * NA;
        K = KA;  N = NA;
    } else {
        src = srcB + (size_t)(z - NLAYER) * KB * NB;  dst = dstB + (size_t)(z - NLAYER) * KB * NB;
        K = KB;  N = NB;
    }
    int bn = blockIdx.x * 32, bk = blockIdx.y * 64;
    if (bn >= N || bk >= K) return;
    int tx = threadIdx.x & 31, ty = threadIdx.x >> 5;  // 32 x 8
#pragma unroll
    for (int i = 0; i < 8; i++)
        t[ty + i * 8][tx] = src[(size_t)(bk + ty + i * 8) * N + bn + tx];
    __syncthreads();
    int nl = threadIdx.x >> 3;           // 0..31
    int kp = threadIdx.x & 7;            // 0..7
    __half* drow = dst + (size_t)(bn + nl) * K + bk;
#pragma unroll
    for (int j = 0; j < 4; j++) {
        int k2 = kp + j * 8;             // 0..31 half2 slots
        *(__half2*)&drow[2 * k2] = __floats2half2_rn(t[2 * k2][nl], t[2 * k2 + 1][nl]);
    }
}

// ======================= mma.sync fp16 GEMM (4-buffer ring, 1 sync/stage) =======================
// 128 threads, 4 warps. MT=4: 128x128 tile (64x64 warp tile); MT=2: 64x128 tile.
// K-chunk 32, 4-deep cp.async ring, XOR-swizzled 64B-row smem, B via ldsm_x4.
// EPI: 0=none(fp32 C), 1=+bias(fp32), 2=+bias+residual(fp32),
//      3=+bias,GELU->fp16, 5=+bias->fp16
// RAGGED: guard B rows / C cols against N (lm_head)
template <int EPI, int RAGGED, int MT>
__global__ void __launch_bounds__(128) tc_gemm(const __half* __restrict__ A,
                                               const __half* __restrict__ B,
                                               const float* __restrict__ bias,
                                               const float* __restrict__ R,
                                               float* __restrict__ C,
                                               __half* __restrict__ Ch,
                                               int N, int K) {
    constexpr int TILE_M = MT * 32;
    constexpr int REG_B = TILE_M * 64;            // A region bytes
    constexpr int STAGE = REG_B + 128 * 64;       // + B region
    constexpr int MTILES = MROW / TILE_M;

    extern __shared__ char sm[];
    const uint32_t sbase = smem_u32(sm);
    const int tid = threadIdx.x;
    const int warp = tid >> 5, lane = tid & 31;

    // m-inner ordering: consecutive CTAs share the same B tile (L2 reuse)
    const int m0 = (blockIdx.x % MTILES) * TILE_M;
    const int n0 = (blockIdx.x / MTILES) * 128;

    const int warpM = (warp >> 1) * (TILE_M / 2);
    const int warpN = (warp & 1) * 64;

    float acc[MT][8][4];
#pragma unroll
    for (int i = 0; i < MT; i++)
#pragma unroll
        for (int j = 0; j < 8; j++)
#pragma unroll
            for (int c = 0; c < 4; c++) acc[i][j][c] = 0.f;

    const int NK = K >> 5;

    auto fill = [&](int s) {
        if (s >= NK) { return; }
        const uint32_t st = sbase + (s & 3) * STAGE;
        const int k0 = s << 5;
#pragma unroll
        for (int u = 0; u < MT; u++) {
            int id = tid + (u << 7);
            int row = id >> 2, c = id & 3;
            cp16(st + swz64(row, c), A + (size_t)(m0 + row) * K + k0 + c * 8);
        }
#pragma unroll
        for (int u = 0; u < 4; u++) {
            int id = tid + (u << 7);
            int row = id >> 2, c = id & 3;
            uint32_t so = st + REG_B + swz64(row, c);
            int gn = n0 + row;
            if (RAGGED) {
                int ok = gn < N;
                int gnc = ok ? gn : 0;
                cp16z(so, B + (size_t)gnc * K + k0 + c * 8, ok);
            } else {
                cp16(so, B + (size_t)gn * K + k0 + c * 8);
            }
        }
    };

    fill(0); CP_COMMIT();
    fill(1); CP_COMMIT();
    fill(2); CP_COMMIT();

    // per-lane fragment address components (swizzled)
    const int ar = warpM + (lane & 15);
    const uint32_t abase = (uint32_t)(ar * 64);
    const int axr = (ar >> 1) & 3;
    const int ahalf = lane >> 4;

    const int br = warpN + (lane & 7) + ((lane >> 4) << 3);
    const uint32_t bbase = (uint32_t)(REG_B + br * 64);
    const int bxr = (br >> 1) & 3;
    const int bhalf = (lane >> 3) & 1;

    for (int kt = 0; kt < NK; kt++) {
        CP_WAIT2();
        __syncthreads();
        // refill the buffer consumed LAST stage (all threads are past it)
        fill(kt + 3);
        CP_COMMIT();

        const uint32_t st = sbase + (kt & 3) * STAGE;
#pragma unroll
        for (int ks = 0; ks < 2; ks++) {
            uint32_t af[MT][4];
#pragma unroll
            for (int mt = 0; mt < MT; mt++)
                ldsm_x4(st + abase + mt * 1024 + (((ks * 2 + ahalf) ^ axr) << 4), af[mt]);
#pragma unroll
            for (int nh = 0; nh < 2; nh++) {
                uint32_t bf4[2][4];
#pragma unroll
                for (int j2 = 0; j2 < 2; j2++)
                    ldsm_x4(st + bbase + (nh * 2 + j2) * 1024 +
                            (((ks * 2 + bhalf) ^ bxr) << 4), bf4[j2]);
#pragma unroll
                for (int mt = 0; mt < MT; mt++)
#pragma unroll
                    for (int j = 0; j < 4; j++)
                        mma_fp16(acc[mt][nh * 4 + j], af[mt], &bf4[j >> 1][(j & 1) * 2]);
            }
        }
    }

    // ---- epilogue ----
    const int g = lane >> 2, t4 = lane & 3;
#pragma unroll
    for (int mt = 0; mt < MT; mt++) {
#pragma unroll
        for (int nt = 0; nt < 8; nt++) {
            int col = n0 + warpN + nt * 8 + 2 * t4;
            int row0 = m0 + warpM + mt * 16 + g;
#pragma unroll
            for (int h = 0; h < 2; h++) {
                int rowg = row0 + h * 8;
                float v0 = acc[mt][nt][2 * h];
                float v1 = acc[mt][nt][2 * h + 1];
                if (RAGGED) {
                    if (col < N) {
                        if (EPI >= 1) v0 += bias[col];
                        C[(size_t)rowg * N + col] = v0;
                    }
                    if (col + 1 < N) {
                        if (EPI >= 1) v1 += bias[col + 1];
                        C[(size_t)rowg * N + col + 1] = v1;
                    }
                } else if (EPI == 3 || EPI == 5) {
                    v0 += bias[col]; v1 += bias[col + 1];
                    if (EPI == 3) { v0 = gelu_f(v0); v1 = gelu_f(v1); }
                    *(__half2*)&Ch[(size_t)rowg * N + col] = __floats2half2_rn(v0, v1);
                } else {
                    if (EPI >= 1) { v0 += bias[col]; v1 += bias[col + 1]; }
                    if (EPI == 2) {
                        v0 += R[(size_t)rowg * N + col];
                        v1 += R[(size_t)rowg * N + col + 1];
                    }
                    float2 o = make_float2(v0, v1);
                    *(float2*)&C[(size_t)rowg * N + col] = o;
                }
            }
        }
    }
}

#define SMEM_MT4 (4 * (128 * 64 + 128 * 64))   // 65536
#define SMEM_MT2 (4 * (64 * 64 + 128 * 64))    // 49152

// ---------------- embedding: x = wte[idx] + wpe[t] ----------------
__global__ void embed_kernel(const int* __restrict__ idx,
                             const float* __restrict__ wte,
                             const float* __restrict__ wpe,
                             float* __restrict__ x) {
    int i = blockIdx.x * blockDim.x + threadIdx.x;
    if (i >= MROW * EMB) return;
    int row = i / EMB;
    int e = i - row * EMB;
    int t = row % TLEN;
    x[i] = wte[(size_t)idx[row] * EMB + e] + wpe[(size_t)t * EMB + e];
}

// ---------------- layernorm: fp32 in, fp16 out ----------------
__global__ void __launch_bounds__(256) ln_kernel(const float* __restrict__ x,
                                                 const float* __restrict__ w,
                                                 const float* __restrict__ b,
                                                 __half* __restrict__ o16) {
    __shared__ float red[8];
    __shared__ float s_mean, s_var;
    int row = blockIdx.x;
    int tid = threadIdx.x;
    int warp = tid >> 5, lane = tid & 31;
    const float* xr = x + (size_t)row * EMB;

    float v0 = xr[tid], v1 = xr[tid + 256], v2 = xr[tid + 512];
    float s = v0 + v1 + v2;
#pragma unroll
    for (int o = 16; o; o >>= 1) s += __shfl_xor_sync(0xffffffffu, s, o);
    if (lane == 0) red[warp] = s;
    __syncthreads();
    if (tid == 0) {
        float t = 0.f;
#pragma unroll
        for (int i = 0; i < 8; i++) t += red[i];
        s_mean = t * (1.0f / EMB);
    }
    __syncthreads();
    float m = s_mean;
    float d0 = v0 - m, d1 = v1 - m, d2 = v2 - m;
    float q = d0 * d0 + d1 * d1 + d2 * d2;
#pragma unroll
    for (int o = 16; o; o >>= 1) q += __shfl_xor_sync(0xffffffffu, q, o);
    if (lane == 0) red[warp] = q;
    __syncthreads();
    if (tid == 0) {
        float t = 0.f;
#pragma unroll
        for (int i = 0; i < 8; i++) t += red[i];
        s_var = t * (1.0f / EMB);
    }
    __syncthreads();
    float r = rsqrtf(s_var + 1e-5f);
    size_t base = (size_t)row * EMB;
#pragma unroll
    for (int u = 0; u < 3; u++) {
        int e = tid + u * 256;
        float d = (u == 0 ? d0 : (u == 1 ? d1 : d2));
        o16[base + e] = __float2half_rn(d * r * w[e] + b[e]);
    }
}

// ---------------- flash attention: tensor cores, 64q x 64k tiles ----------------
#define ASTR 144

__global__ void __launch_bounds__(128) fattn_kernel(const __half* __restrict__ qkv,
                                                    __half* __restrict__ y) {
    __shared__ __align__(16) char smem[3 * 64 * ASTR];
    const uint32_t sQ = smem_u32(smem);
    const uint32_t sK = sQ + 64 * ASTR;
    const uint32_t sV = sK + 64 * ASTR;
    const int tid = threadIdx.x, warp = tid >> 5, lane = tid & 31;
    const int g = lane >> 2, t4 = lane & 3;
    const int bh = blockIdx.x;
    const int b = bh / NHEAD, h = bh % NHEAD;
    const int qb = blockIdx.y;
    const size_t row0g = (size_t)(b * TLEN);

#pragma unroll
    for (int u = 0; u < 4; u++) {
        int id = tid + u * 128;
        int row = id >> 3, c = id & 7;
        const uint4* src = (const uint4*)(qkv + (row0g + qb * 64 + row) * (3 * EMB) + h * HEADD + c * 8);
        *(uint4*)(smem + row * ASTR + c * 16) = *src;
    }
    __syncthreads();

    uint32_t qf[4][4];
    {
        uint32_t aoffQ = sQ + (warp * 16 + (lane & 15)) * ASTR + ((lane >> 4) * 16);
#pragma unroll
        for (int ks = 0; ks < 4; ks++) ldsm_x4(aoffQ + ks * 32, qf[ks]);
    }

    float m0 = -1e30f, m1 = -1e30f, l0 = 0.f, l1 = 0.f;
    float O[8][4];
#pragma unroll
    for (int j = 0; j < 8; j++)
#pragma unroll
        for (int e = 0; e < 4; e++) O[j][e] = 0.f;

    const uint32_t boffK = sK + (lane & 7) * ASTR + ((lane >> 3) & 1) * 16;
    const uint32_t boffV = sV + ((lane & 7) + ((lane >> 3) & 1) * 8) * ASTR;

    for (int c = 0; c <= qb; c++) {
        __syncthreads();
#pragma unroll
        for (int u = 0; u < 4; u++) {
            int id = tid + u * 128;
            int row = id >> 3, cc = id & 7;
            const __half* src = qkv + (row0g + c * 64 + row) * (3 * EMB) + EMB + h * HEADD + cc * 8;
            *(uint4*)(smem + 64 * ASTR + row * ASTR + cc * 16) = *(const uint4*)src;
            *(uint4*)(smem + 128 * ASTR + row * ASTR + cc * 16) = *(const uint4*)(src + EMB);
        }
        __syncthreads();

        float S[8][4];
#pragma unroll
        for (int j = 0; j < 8; j++)
#pragma unroll
            for (int e = 0; e < 4; e++) S[j][e] = 0.f;
#pragma unroll
        for (int ks = 0; ks < 4; ks++) {
#pragma unroll
            for (int j = 0; j < 8; j++) {
                uint32_t bf[2];
                ldsm_x2(boffK + j * (8 * ASTR) + ks * 32, bf);
                mma_fp16(S[j], qf[ks], bf);
            }
        }
#pragma unroll
        for (int j = 0; j < 8; j++)
#pragma unroll
            for (int e = 0; e < 4; e++) S[j][e] *= 0.125f;
        if (c == qb) {
            int q0l = warp * 16 + g, q1l = q0l + 8;
#pragma unroll
            for (int j = 0; j < 8; j++) {
                int k0 = j * 8 + 2 * t4;
                if (k0 > q0l)     S[j][0] = -1e30f;
                if (k0 + 1 > q0l) S[j][1] = -1e30f;
                if (k0 > q1l)     S[j][2] = -1e30f;
                if (k0 + 1 > q1l) S[j][3] = -1e30f;
            }
        }
        float rm0 = -1e30f, rm1 = -1e30f;
#pragma unroll
        for (int j = 0; j < 8; j++) {
            rm0 = fmaxf(rm0, fmaxf(S[j][0], S[j][1]));
            rm1 = fmaxf(rm1, fmaxf(S[j][2], S[j][3]));
        }
        rm0 = fmaxf(rm0, __shfl_xor_sync(0xffffffffu, rm0, 1));
        rm0 = fmaxf(rm0, __shfl_xor_sync(0xffffffffu, rm0, 2));
        rm1 = fmaxf(rm1, __shfl_xor_sync(0xffffffffu, rm1, 1));
        rm1 = fmaxf(rm1, __shfl_xor_sync(0xffffffffu, rm1, 2));
        float mn0 = fmaxf(m0, rm0), mn1 = fmaxf(m1, rm1);
        float corr0 = __expf(m0 - mn0), corr1 = __expf(m1 - mn1);
        m0 = mn0; m1 = mn1;
        float rs0 = 0.f, rs1 = 0.f;
#pragma unroll
        for (int j = 0; j < 8; j++) {
            S[j][0] = __expf(S[j][0] - mn0);
            S[j][1] = __expf(S[j][1] - mn0);
            S[j][2] = __expf(S[j][2] - mn1);
            S[j][3] = __expf(S[j][3] - mn1);
            rs0 += S[j][0] + S[j][1];
            rs1 += S[j][2] + S[j][3];
        }
        rs0 += __shfl_xor_sync(0xffffffffu, rs0, 1);
        rs0 += __shfl_xor_sync(0xffffffffu, rs0, 2);
        rs1 += __shfl_xor_sync(0xffffffffu, rs1, 1);
        rs1 += __shfl_xor_sync(0xffffffffu, rs1, 2);
        l0 = l0 * corr0 + rs0;
        l1 = l1 * corr1 + rs1;
#pragma unroll
        for (int j = 0; j < 8; j++) {
            O[j][0] *= corr0; O[j][1] *= corr0;
            O[j][2] *= corr1; O[j][3] *= corr1;
        }
#pragma unroll
        for (int kc = 0; kc < 4; kc++) {
            uint32_t pa[4];
            pa[0] = packh2(S[2 * kc][0],     S[2 * kc][1]);
            pa[1] = packh2(S[2 * kc][2],     S[2 * kc][3]);
            pa[2] = packh2(S[2 * kc + 1][0], S[2 * kc + 1][1]);
            pa[3] = packh2(S[2 * kc + 1][2], S[2 * kc + 1][3]);
#pragma unroll
            for (int jd = 0; jd < 8; jd++) {
                uint32_t bv[2];
                ldsm_x2t(boffV + kc * (16 * ASTR) + jd * 16, bv);
                mma_fp16(O[jd], pa, bv);
            }
        }
    }

    float i0 = 1.0f / l0, i1 = 1.0f / l1;
    int qrow = qb * 64 + warp * 16 + g;
    size_t ybase = (row0g + qrow) * EMB + h * HEADD;
#pragma unroll
    for (int jd = 0; jd < 8; jd++) {
        int col = jd * 8 + 2 * t4;
        *(__half2*)&y[ybase + col] = __floats2half2_rn(O[jd][0] * i0, O[jd][1] * i0);
        *(__half2*)&y[ybase + 8 * EMB + col] = __floats2half2_rn(O[jd][2] * i1, O[jd][3] * i1);
    }
}

// ---------------- host launch ----------------
extern "C" void kernel_launch(void* const* d_in, const int* in_sizes, int n_in,
                              void* d_out, int out_size) {
    (void)in_sizes; (void)n_in; (void)out_size;
    const int*   x_idx  = (const int*)d_in[0];
    const float* wte    = (const float*)d_in[1];
    const float* wpe    = (const float*)d_in[2];
    const float* ln1_w  = (const float*)d_in[3];
    const float* ln1_b  = (const float*)d_in[4];
    const float* attn_w = (const float*)d_in[5];
    const float* attn_b = (const float*)d_in[6];
    const float* proj_w = (const float*)d_in[7];
    const float* proj_b = (const float*)d_in[8];
    const float* ln2_w  = (const float*)d_in[9];
    const float* ln2_b  = (const float*)d_in[10];
    const float* fc1_w  = (const float*)d_in[11];
    const float* fc1_b  = (const float*)d_in[12];
    const float* fc2_w  = (const float*)d_in[13];
    const float* fc2_b  = (const float*)d_in[14];
    const float* lnf_w  = (const float*)d_in[15];
    const float* lnf_b  = (const float*)d_in[16];
    float* out = (float*)d_out;

    float *gx;
    __half *gh, *gqkv, *gy, *gf1;
    __half *wq, *wp, *w1, *w2, *wt;
    cudaGetSymbolAddress((void**)&gx,   g_x);
    cudaGetSymbolAddress((void**)&gh,   g_h);
    cudaGetSymbolAddress((void**)&gqkv, g_qkv16);
    cudaGetSymbolAddress((void**)&gy,   g_y);
    cudaGetSymbolAddress((void**)&gf1,  g_f1);
    cudaGetSymbolAddress((void**)&wq,   g_wqkv);
    cudaGetSymbolAddress((void**)&wp,   g_wproj);
    cudaGetSymbolAddress((void**)&w1,   g_wf1);
    cudaGetSymbolAddress((void**)&w2,   g_wf2);
    cudaGetSymbolAddress((void**)&wt,   g_wte16);

    cudaFuncSetAttribute(tc_gemm<5, 0, 4>, cudaFuncAttributeMaxDynamicSharedMemorySize, SMEM_MT4);
    cudaFuncSetAttribute(tc_gemm<2, 0, 2>, cudaFuncAttributeMaxDynamicSharedMemorySize, SMEM_MT2);
    cudaFuncSetAttribute(tc_gemm<3, 0, 4>, cudaFuncAttributeMaxDynamicSharedMemorySize, SMEM_MT4);
    cudaFuncSetAttribute(tc_gemm<0, 1, 4>, cudaFuncAttributeMaxDynamicSharedMemorySize, SMEM_MT4);

    // launch order keeps the first qkv GEMM at launch #6 for ncu (-s 5 -c 1)
    embed_kernel<<<(MROW * EMB + 255) / 256, 256>>>(x_idx, wte, wpe, gx);          // 1
    cvtT2_kernel<<<dim3(96, 12, 2 * NLAYER), 256>>>(                               // 2
        attn_w, wq, EMB, 3 * EMB, fc1_w, w1, EMB, 4 * EMB);
    cvtT2_kernel<<<dim3(24, 48, 2 * NLAYER), 256>>>(                               // 3
        proj_w, wp, EMB, EMB, fc2_w, w2, 4 * EMB, EMB);
    cvt_kernel<<<(VOCAB * EMB / 4 + 255) / 256, 256>>>(wte, wt, VOCAB * EMB / 4);  // 4

    for (int l = 0; l < NLAYER; l++) {
        ln_kernel<<<MROW, 256>>>(gx, ln1_w + (size_t)l * EMB, ln1_b + (size_t)l * EMB, gh);  // 5

        // qkv = h @ attn_w + attn_b -> fp16  (N=2304, 128x128 tiles)              // 6 <- ncu
        tc_gemm<5, 0, 4><<<32 * 18, 128, SMEM_MT4>>>(
            gh, wq + (size_t)l * 3 * EMB * EMB,
            attn_b + (size_t)l * 3 * EMB, nullptr, nullptr, gqkv, 3 * EMB, EMB);

        fattn_kernel<<<dim3(BATCH * NHEAD, TLEN / 64), 128>>>(gqkv, gy);

        // x = x + y @ proj_w + proj_b  (N=768, 64x128 tiles -> 384 CTAs)
        tc_gemm<2, 0, 2><<<64 * 6, 128, SMEM_MT2>>>(
            gy, wp + (size_t)l * EMB * EMB,
            proj_b + (size_t)l * EMB, gx, gx, nullptr, EMB, EMB);

        ln_kernel<<<MROW, 256>>>(gx, ln2_w + (size_t)l * EMB, ln2_b + (size_t)l * EMB, gh);

        // f1 = gelu(h @ fc1_w + fc1_b) -> fp16  (N=3072, 128x128 tiles)
        tc_gemm<3, 0, 4><<<32 * 24, 128, SMEM_MT4>>>(
            gh, w1 + (size_t)l * 4 * EMB * EMB,
            fc1_b + (size_t)l * 4 * EMB, nullptr, nullptr, gf1, 4 * EMB, EMB);

        // x = x + f1 @ fc2_w + fc2_b   (N=768, K=3072, 64x128 tiles -> 384 CTAs)
        tc_gemm<2, 0, 2><<<64 * 6, 128, SMEM_MT2>>>(
            gf1, w2 + (size_t)l * 4 * EMB * EMB,
            fc2_b + (size_t)l * EMB, gx, gx, nullptr, EMB, 4 * EMB);
    }

    ln_kernel<<<MROW, 256>>>(gx, lnf_w, lnf_b, gh);

    // logits = h @ wte^T  (N=50257, 128x128 tiles, ragged)
    tc_gemm<0, 1, 4><<<32 * 393, 128, SMEM_MT4>>>(
        gh, wt, nullptr, nullptr, out, nullptr, VOCAB, EMB);
}

// round 17
// speedup vs baseline: 1.3831x; 1.0449x over previous
#include <cuda_runtime.h>
#include <cuda_fp16.h>
#include <math.h>
#include <stdint.h>

// GPT-2 small config
#define BATCH 4
#define TLEN  1024
#define EMB   768
#define NLAYER 12
#define VOCAB 50257
#define NHEAD 12
#define HEADD 64
#define MROW  (BATCH * TLEN)   // 4096

// ---------------- scratch (device globals; no allocation allowed) ----------------
__device__ float g_x[MROW * EMB];        // residual stream (fp32)

// fp16 activations
__device__ __half g_h[MROW * EMB];
__device__ __half g_qkv16[MROW * 3 * EMB];
__device__ __half g_y[MROW * EMB];
__device__ __half g_f1[MROW * 4 * EMB];

// fp16 weights, stored [N][K] (K-major rows) for ldmatrix col access
__device__ __half g_wqkv[NLAYER * 3 * EMB * EMB];
__device__ __half g_wproj[NLAYER * EMB * EMB];
__device__ __half g_wf1[NLAYER * 4 * EMB * EMB];
__device__ __half g_wf2[NLAYER * 4 * EMB * EMB];
__device__ __half g_wte16[VOCAB * EMB];

// ======================= helpers =======================
__device__ __forceinline__ uint32_t smem_u32(const void* p) {
    uint32_t a;
    asm("{ .reg .u64 t; cvta.to.shared.u64 t, %1; cvt.u32.u64 %0, t; }"
        : "=r"(a) : "l"(p));
    return a;
}
__device__ __forceinline__ void ldsm_x4(uint32_t addr, uint32_t* r) {
    asm volatile("ldmatrix.sync.aligned.m8n8.x4.shared.b16 {%0,%1,%2,%3}, [%4];"
                 : "=r"(r[0]), "=r"(r[1]), "=r"(r[2]), "=r"(r[3]) : "r"(addr));
}
__device__ __forceinline__ void ldsm_x2(uint32_t addr, uint32_t* r) {
    asm volatile("ldmatrix.sync.aligned.m8n8.x2.shared.b16 {%0,%1}, [%2];"
                 : "=r"(r[0]), "=r"(r[1]) : "r"(addr));
}
__device__ __forceinline__ void ldsm_x2t(uint32_t addr, uint32_t* r) {
    asm volatile("ldmatrix.sync.aligned.m8n8.x2.trans.shared.b16 {%0,%1}, [%2];"
                 : "=r"(r[0]), "=r"(r[1]) : "r"(addr));
}
__device__ __forceinline__ void mma_fp16(float* d, const uint32_t* a, const uint32_t* b) {
    asm volatile(
        "mma.sync.aligned.m16n8k16.row.col.f32.f16.f16.f32 "
        "{%0,%1,%2,%3}, {%4,%5,%6,%7}, {%8,%9}, {%0,%1,%2,%3};"
        : "+f"(d[0]), "+f"(d[1]), "+f"(d[2]), "+f"(d[3])
        : "r"(a[0]), "r"(a[1]), "r"(a[2]), "r"(a[3]), "r"(b[0]), "r"(b[1]));
}
__device__ __forceinline__ void cp16(uint32_t saddr, const void* g) {
    asm volatile("cp.async.cg.shared.global [%0], [%1], 16;" :: "r"(saddr), "l"(g));
}
__device__ __forceinline__ void cp16z(uint32_t saddr, const void* g, int ok) {
    int sz = ok ? 16 : 0;
    asm volatile("cp.async.cg.shared.global [%0], [%1], 16, %2;" :: "r"(saddr), "l"(g), "r"(sz));
}
#define CP_COMMIT() asm volatile("cp.async.commit_group;" ::: "memory")
#define CP_WAIT2()  asm volatile("cp.async.wait_group 2;" ::: "memory")

__device__ __forceinline__ uint32_t packh2(float a, float b) {
    __half2 t = __floats2half2_rn(a, b);
    return reinterpret_cast<uint32_t&>(t);
}
__device__ __forceinline__ float gelu_f(float x) {
    return 0.5f * x * (1.0f + erff(x * 0.7071067811865476f));
}
// XOR-swizzled smem address: 64B rows, 4x16B slots, conflict-free for
// both ldmatrix 8-row phases and cp.async 8-thread store phases.
__device__ __forceinline__ uint32_t swz64(int row, int c) {
    return (uint32_t)(row * 64 + ((c ^ ((row >> 1) & 3)) << 4));
}

// ======================= weight convert kernels =======================
__global__ void cvt_kernel(const float* __restrict__ src,
                           __half* __restrict__ dst, int n4) {
    int i = blockIdx.x * blockDim.x + threadIdx.x;
    if (i >= n4) return;
    float4 v = ((const float4*)src)[i];
    uint2 o;
    o.x = packh2(v.x, v.y);
    o.y = packh2(v.z, v.w);
    ((uint2*)dst)[i] = o;
}

// transpose+convert for TWO weight families; 32n x 64k tiles, half2 stores.
__global__ void __launch_bounds__(256) cvtT2_kernel(
    const float* __restrict__ srcA, __half* __restrict__ dstA, int KA, int NA,
    const float* __restrict__ srcB, __half* __restrict__ dstB, int KB, int NB) {
    __shared__ float t[64][33];
    int z = blockIdx.z;
    const float* src;  __half* dst;  int K, N;
    if (z < NLAYER) {
        src = srcA + (size_t)z * KA * NA;  dst = dstA + (size_t)z * KA * NA;
        K = KA;  N = NA;
    } else {
        src = srcB + (size_t)(z - NLAYER) * KB * NB;  dst = dstB + (size_t)(z - NLAYER) * KB * NB;
        K = KB;  N = NB;
    }
    int bn = blockIdx.x * 32, bk = blockIdx.y * 64;
    if (bn >= N || bk >= K) return;
    int tx = threadIdx.x & 31, ty = threadIdx.x >> 5;  // 32 x 8
#pragma unroll
    for (int i = 0; i < 8; i++)
        t[ty + i * 8][tx] = src[(size_t)(bk + ty + i * 8) * N + bn + tx];
    __syncthreads();
    int nl = threadIdx.x >> 3;           // 0..31
    int kp = threadIdx.x & 7;            // 0..7
    __half* drow = dst + (size_t)(bn + nl) * K + bk;
#pragma unroll
    for (int j = 0; j < 4; j++) {
        int k2 = kp + j * 8;             // 0..31 half2 slots
        *(__half2*)&drow[2 * k2] = __floats2half2_rn(t[2 * k2][nl], t[2 * k2 + 1][nl]);
    }
}

// ======================= mma.sync fp16 GEMM (4-buffer ring, 1 sync/stage) =======================
// 128 threads, 4 warps. MT=4: 128x128 tile (64x64 warp tile), min 3 CTAs/SM;
// MT=2: 64x128 tile, min 4 CTAs/SM.
// K-chunk 32, 4-deep cp.async ring, XOR-swizzled 64B-row smem, B via ldsm_x4.
// EPI: 0=none(fp32 C), 1=+bias(fp32), 2=+bias+residual(fp32),
//      3=+bias,GELU->fp16, 5=+bias->fp16
// RAGGED: guard B rows / C cols against N (lm_head)
template <int EPI, int RAGGED, int MT>
__global__ void __launch_bounds__(128, (MT == 4) ? 3 : 4)
tc_gemm(const __half* __restrict__ A,
        const __half* __restrict__ B,
        const float* __restrict__ bias,
        const float* __restrict__ R,
        float* __restrict__ C,
        __half* __restrict__ Ch,
        int N, int K) {
    constexpr int TILE_M = MT * 32;
    constexpr int REG_B = TILE_M * 64;            // A region bytes
    constexpr int STAGE = REG_B + 128 * 64;       // + B region
    constexpr int MTILES = MROW / TILE_M;

    extern __shared__ char sm[];
    const uint32_t sbase = smem_u32(sm);
    const int tid = threadIdx.x;
    const int warp = tid >> 5, lane = tid & 31;

    // m-inner ordering: consecutive CTAs share the same B tile (L2 reuse)
    const int m0 = (blockIdx.x % MTILES) * TILE_M;
    const int n0 = (blockIdx.x / MTILES) * 128;

    const int warpM = (warp >> 1) * (TILE_M / 2);
    const int warpN = (warp & 1) * 64;

    float acc[MT][8][4];
#pragma unroll
    for (int i = 0; i < MT; i++)
#pragma unroll
        for (int j = 0; j < 8; j++)
#pragma unroll
            for (int c = 0; c < 4; c++) acc[i][j][c] = 0.f;

    const int NK = K >> 5;

    auto fill = [&](int s) {
        if (s >= NK) { return; }
        const uint32_t st = sbase + (s & 3) * STAGE;
        const int k0 = s << 5;
#pragma unroll
        for (int u = 0; u < MT; u++) {
            int id = tid + (u << 7);
            int row = id >> 2, c = id & 3;
            cp16(st + swz64(row, c), A + (size_t)(m0 + row) * K + k0 + c * 8);
        }
#pragma unroll
        for (int u = 0; u < 4; u++) {
            int id = tid + (u << 7);
            int row = id >> 2, c = id & 3;
            uint32_t so = st + REG_B + swz64(row, c);
            int gn = n0 + row;
            if (RAGGED) {
                int ok = gn < N;
                int gnc = ok ? gn : 0;
                cp16z(so, B + (size_t)gnc * K + k0 + c * 8, ok);
            } else {
                cp16(so, B + (size_t)gn * K + k0 + c * 8);
            }
        }
    };

    fill(0); CP_COMMIT();
    fill(1); CP_COMMIT();
    fill(2); CP_COMMIT();

    // per-lane fragment address components (swizzled)
    const int ar = warpM + (lane & 15);
    const uint32_t abase = (uint32_t)(ar * 64);
    const int axr = (ar >> 1) & 3;
    const int ahalf = lane >> 4;

    const int br = warpN + (lane & 7) + ((lane >> 4) << 3);
    const uint32_t bbase = (uint32_t)(REG_B + br * 64);
    const int bxr = (br >> 1) & 3;
    const int bhalf = (lane >> 3) & 1;

    for (int kt = 0; kt < NK; kt++) {
        CP_WAIT2();
        __syncthreads();
        // refill the buffer consumed LAST stage (all threads are past it)
        fill(kt + 3);
        CP_COMMIT();

        const uint32_t st = sbase + (kt & 3) * STAGE;
#pragma unroll
        for (int ks = 0; ks < 2; ks++) {
            uint32_t af[MT][4];
#pragma unroll
            for (int mt = 0; mt < MT; mt++)
                ldsm_x4(st + abase + mt * 1024 + (((ks * 2 + ahalf) ^ axr) << 4), af[mt]);
#pragma unroll
            for (int nh = 0; nh < 2; nh++) {
                uint32_t bf4[2][4];
#pragma unroll
                for (int j2 = 0; j2 < 2; j2++)
                    ldsm_x4(st + bbase + (nh * 2 + j2) * 1024 +
                            (((ks * 2 + bhalf) ^ bxr) << 4), bf4[j2]);
#pragma unroll
                for (int mt = 0; mt < MT; mt++)
#pragma unroll
                    for (int j = 0; j < 4; j++)
                        mma_fp16(acc[mt][nh * 4 + j], af[mt], &bf4[j >> 1][(j & 1) * 2]);
            }
        }
    }

    // ---- epilogue ----
    const int g = lane >> 2, t4 = lane & 3;
#pragma unroll
    for (int mt = 0; mt < MT; mt++) {
#pragma unroll
        for (int nt = 0; nt < 8; nt++) {
            int col = n0 + warpN + nt * 8 + 2 * t4;
            int row0 = m0 + warpM + mt * 16 + g;
#pragma unroll
            for (int h = 0; h < 2; h++) {
                int rowg = row0 + h * 8;
                float v0 = acc[mt][nt][2 * h];
                float v1 = acc[mt][nt][2 * h + 1];
                if (RAGGED) {
                    if (col < N) {
                        if (EPI >= 1) v0 += bias[col];
                        C[(size_t)rowg * N + col] = v0;
                    }
                    if (col + 1 < N) {
                        if (EPI >= 1) v1 += bias[col + 1];
                        C[(size_t)rowg * N + col + 1] = v1;
                    }
                } else if (EPI == 3 || EPI == 5) {
                    v0 += bias[col]; v1 += bias[col + 1];
                    if (EPI == 3) { v0 = gelu_f(v0); v1 = gelu_f(v1); }
                    *(__half2*)&Ch[(size_t)rowg * N + col] = __floats2half2_rn(v0, v1);
                } else {
                    if (EPI >= 1) { v0 += bias[col]; v1 += bias[col + 1]; }
                    if (EPI == 2) {
                        v0 += R[(size_t)rowg * N + col];
                        v1 += R[(size_t)rowg * N + col + 1];
                    }
                    float2 o = make_float2(v0, v1);
                    *(float2*)&C[(size_t)rowg * N + col] = o;
                }
            }
        }
    }
}

#define SMEM_MT4 (4 * (128 * 64 + 128 * 64))   // 65536
#define SMEM_MT2 (4 * (64 * 64 + 128 * 64))    // 49152

// ---------------- embedding: x = wte[idx] + wpe[t] ----------------
__global__ void embed_kernel(const int* __restrict__ idx,
                             const float* __restrict__ wte,
                             const float* __restrict__ wpe,
                             float* __restrict__ x) {
    int i = blockIdx.x * blockDim.x + threadIdx.x;
    if (i >= MROW * EMB) return;
    int row = i / EMB;
    int e = i - row * EMB;
    int t = row % TLEN;
    x[i] = wte[(size_t)idx[row] * EMB + e] + wpe[(size_t)t * EMB + e];
}

// ---------------- layernorm: fp32 in, fp16 out ----------------
__global__ void __launch_bounds__(256) ln_kernel(const float* __restrict__ x,
                                                 const float* __restrict__ w,
                                                 const float* __restrict__ b,
                                                 __half* __restrict__ o16) {
    __shared__ float red[8];
    __shared__ float s_mean, s_var;
    int row = blockIdx.x;
    int tid = threadIdx.x;
    int warp = tid >> 5, lane = tid & 31;
    const float* xr = x + (size_t)row * EMB;

    float v0 = xr[tid], v1 = xr[tid + 256], v2 = xr[tid + 512];
    float s = v0 + v1 + v2;
#pragma unroll
    for (int o = 16; o; o >>= 1) s += __shfl_xor_sync(0xffffffffu, s, o);
    if (lane == 0) red[warp] = s;
    __syncthreads();
    if (tid == 0) {
        float t = 0.f;
#pragma unroll
        for (int i = 0; i < 8; i++) t += red[i];
        s_mean = t * (1.0f / EMB);
    }
    __syncthreads();
    float m = s_mean;
    float d0 = v0 - m, d1 = v1 - m, d2 = v2 - m;
    float q = d0 * d0 + d1 * d1 + d2 * d2;
#pragma unroll
    for (int o = 16; o; o >>= 1) q += __shfl_xor_sync(0xffffffffu, q, o);
    if (lane == 0) red[warp] = q;
    __syncthreads();
    if (tid == 0) {
        float t = 0.f;
#pragma unroll
        for (int i = 0; i < 8; i++) t += red[i];
        s_var = t * (1.0f / EMB);
    }
    __syncthreads();
    float r = rsqrtf(s_var + 1e-5f);
    size_t base = (size_t)row * EMB;
#pragma unroll
    for (int u = 0; u < 3; u++) {
        int e = tid + u * 256;
        float d = (u == 0 ? d0 : (u == 1 ? d1 : d2));
        o16[base + e] = __float2half_rn(d * r * w[e] + b[e]);
    }
}

// ---------------- flash attention: tensor cores, 64q x 64k tiles ----------------
#define ASTR 144

__global__ void __launch_bounds__(128) fattn_kernel(const __half* __restrict__ qkv,
                                                    __half* __restrict__ y) {
    __shared__ __align__(16) char smem[3 * 64 * ASTR];
    const uint32_t sQ = smem_u32(smem);
    const uint32_t sK = sQ + 64 * ASTR;
    const uint32_t sV = sK + 64 * ASTR;
    const int tid = threadIdx.x, warp = tid >> 5, lane = tid & 31;
    const int g = lane >> 2, t4 = lane & 3;
    const int bh = blockIdx.x;
    const int b = bh / NHEAD, h = bh % NHEAD;
    const int qb = blockIdx.y;
    const size_t row0g = (size_t)(b * TLEN);

#pragma unroll
    for (int u = 0; u < 4; u++) {
        int id = tid + u * 128;
        int row = id >> 3, c = id & 7;
        const uint4* src = (const uint4*)(qkv + (row0g + qb * 64 + row) * (3 * EMB) + h * HEADD + c * 8);
        *(uint4*)(smem + row * ASTR + c * 16) = *src;
    }
    __syncthreads();

    uint32_t qf[4][4];
    {
        uint32_t aoffQ = sQ + (warp * 16 + (lane & 15)) * ASTR + ((lane >> 4) * 16);
#pragma unroll
        for (int ks = 0; ks < 4; ks++) ldsm_x4(aoffQ + ks * 32, qf[ks]);
    }

    float m0 = -1e30f, m1 = -1e30f, l0 = 0.f, l1 = 0.f;
    float O[8][4];
#pragma unroll
    for (int j = 0; j < 8; j++)
#pragma unroll
        for (int e = 0; e < 4; e++) O[j][e] = 0.f;

    const uint32_t boffK = sK + (lane & 7) * ASTR + ((lane >> 3) & 1) * 16;
    const uint32_t boffV = sV + ((lane & 7) + ((lane >> 3) & 1) * 8) * ASTR;

    for (int c = 0; c <= qb; c++) {
        __syncthreads();
#pragma unroll
        for (int u = 0; u < 4; u++) {
            int id = tid + u * 128;
            int row = id >> 3, cc = id & 7;
            const __half* src = qkv + (row0g + c * 64 + row) * (3 * EMB) + EMB + h * HEADD + cc * 8;
            *(uint4*)(smem + 64 * ASTR + row * ASTR + cc * 16) = *(const uint4*)src;
            *(uint4*)(smem + 128 * ASTR + row * ASTR + cc * 16) = *(const uint4*)(src + EMB);
        }
        __syncthreads();

        float S[8][4];
#pragma unroll
        for (int j = 0; j < 8; j++)
#pragma unroll
            for (int e = 0; e < 4; e++) S[j][e] = 0.f;
#pragma unroll
        for (int ks = 0; ks < 4; ks++) {
#pragma unroll
            for (int j = 0; j < 8; j++) {
                uint32_t bf[2];
                ldsm_x2(boffK + j * (8 * ASTR) + ks * 32, bf);
                mma_fp16(S[j], qf[ks], bf);
            }
        }
#pragma unroll
        for (int j = 0; j < 8; j++)
#pragma unroll
            for (int e = 0; e < 4; e++) S[j][e] *= 0.125f;
        if (c == qb) {
            int q0l = warp * 16 + g, q1l = q0l + 8;
#pragma unroll
            for (int j = 0; j < 8; j++) {
                int k0 = j * 8 + 2 * t4;
                if (k0 > q0l)     S[j][0] = -1e30f;
                if (k0 + 1 > q0l) S[j][1] = -1e30f;
                if (k0 > q1l)     S[j][2] = -1e30f;
                if (k0 + 1 > q1l) S[j][3] = -1e30f;
            }
        }
        float rm0 = -1e30f, rm1 = -1e30f;
#pragma unroll
        for (int j = 0; j < 8; j++) {
            rm0 = fmaxf(rm0, fmaxf(S[j][0], S[j][1]));
            rm1 = fmaxf(rm1, fmaxf(S[j][2], S[j][3]));
        }
        rm0 = fmaxf(rm0, __shfl_xor_sync(0xffffffffu, rm0, 1));
        rm0 = fmaxf(rm0, __shfl_xor_sync(0xffffffffu, rm0, 2));
        rm1 = fmaxf(rm1, __shfl_xor_sync(0xffffffffu, rm1, 1));
        rm1 = fmaxf(rm1, __shfl_xor_sync(0xffffffffu, rm1, 2));
        float mn0 = fmaxf(m0, rm0), mn1 = fmaxf(m1, rm1);
        float corr0 = __expf(m0 - mn0), corr1 = __expf(m1 - mn1);
        m0 = mn0; m1 = mn1;
        float rs0 = 0.f, rs1 = 0.f;
#pragma unroll
        for (int j = 0; j < 8; j++) {
            S[j][0] = __expf(S[j][0] - mn0);
            S[j][1] = __expf(S[j][1] - mn0);
            S[j][2] = __expf(S[j][2] - mn1);
            S[j][3] = __expf(S[j][3] - mn1);
            rs0 += S[j][0] + S[j][1];
            rs1 += S[j][2] + S[j][3];
        }
        rs0 += __shfl_xor_sync(0xffffffffu, rs0, 1);
        rs0 += __shfl_xor_sync(0xffffffffu, rs0, 2);
        rs1 += __shfl_xor_sync(0xffffffffu, rs1, 1);
        rs1 += __shfl_xor_sync(0xffffffffu, rs1, 2);
        l0 = l0 * corr0 + rs0;
        l1 = l1 * corr1 + rs1;
#pragma unroll
        for (int j = 0; j < 8; j++) {
            O[j][0] *= corr0; O[j][1] *= corr0;
            O[j][2] *= corr1; O[j][3] *= corr1;
        }
#pragma unroll
        for (int kc = 0; kc < 4; kc++) {
            uint32_t pa[4];
            pa[0] = packh2(S[2 * kc][0],     S[2 * kc][1]);
            pa[1] = packh2(S[2 * kc][2],     S[2 * kc][3]);
            pa[2] = packh2(S[2 * kc + 1][0], S[2 * kc + 1][1]);
            pa[3] = packh2(S[2 * kc + 1][2], S[2 * kc + 1][3]);
#pragma unroll
            for (int jd = 0; jd < 8; jd++) {
                uint32_t bv[2];
                ldsm_x2t(boffV + kc * (16 * ASTR) + jd * 16, bv);
                mma_fp16(O[jd], pa, bv);
            }
        }
    }

    float i0 = 1.0f / l0, i1 = 1.0f / l1;
    int qrow = qb * 64 + warp * 16 + g;
    size_t ybase = (row0g + qrow) * EMB + h * HEADD;
#pragma unroll
    for (int jd = 0; jd < 8; jd++) {
        int col = jd * 8 + 2 * t4;
        *(__half2*)&y[ybase + col] = __floats2half2_rn(O[jd][0] * i0, O[jd][1] * i0);
        *(__half2*)&y[ybase + 8 * EMB + col] = __floats2half2_rn(O[jd][2] * i1, O[jd][3] * i1);
    }
}

// ---------------- host launch ----------------
extern "C" void kernel_launch(void* const* d_in, const int* in_sizes, int n_in,
                              void* d_out, int out_size) {
    (void)in_sizes; (void)n_in; (void)out_size;
    const int*   x_idx  = (const int*)d_in[0];
    const float* wte    = (const float*)d_in[1];
    const float* wpe    = (const float*)d_in[2];
    const float* ln1_w  = (const float*)d_in[3];
    const float* ln1_b  = (const float*)d_in[4];
    const float* attn_w = (const float*)d_in[5];
    const float* attn_b = (const float*)d_in[6];
    const float* proj_w = (const float*)d_in[7];
    const float* proj_b = (const float*)d_in[8];
    const float* ln2_w  = (const float*)d_in[9];
    const float* ln2_b  = (const float*)d_in[10];
    const float* fc1_w  = (const float*)d_in[11];
    const float* fc1_b  = (const float*)d_in[12];
    const float* fc2_w  = (const float*)d_in[13];
    const float* fc2_b  = (const float*)d_in[14];
    const float* lnf_w  = (const float*)d_in[15];
    const float* lnf_b  = (const float*)d_in[16];
    float* out = (float*)d_out;

    float *gx;
    __half *gh, *gqkv, *gy, *gf1;
    __half *wq, *wp, *w1, *w2, *wt;
    cudaGetSymbolAddress((void**)&gx,   g_x);
    cudaGetSymbolAddress((void**)&gh,   g_h);
    cudaGetSymbolAddress((void**)&gqkv, g_qkv16);
    cudaGetSymbolAddress((void**)&gy,   g_y);
    cudaGetSymbolAddress((void**)&gf1,  g_f1);
    cudaGetSymbolAddress((void**)&wq,   g_wqkv);
    cudaGetSymbolAddress((void**)&wp,   g_wproj);
    cudaGetSymbolAddress((void**)&w1,   g_wf1);
    cudaGetSymbolAddress((void**)&w2,   g_wf2);
    cudaGetSymbolAddress((void**)&wt,   g_wte16);

    cudaFuncSetAttribute(tc_gemm<5, 0, 4>, cudaFuncAttributeMaxDynamicSharedMemorySize, SMEM_MT4);
    cudaFuncSetAttribute(tc_gemm<2, 0, 2>, cudaFuncAttributeMaxDynamicSharedMemorySize, SMEM_MT2);
    cudaFuncSetAttribute(tc_gemm<3, 0, 4>, cudaFuncAttributeMaxDynamicSharedMemorySize, SMEM_MT4);
    cudaFuncSetAttribute(tc_gemm<0, 1, 4>, cudaFuncAttributeMaxDynamicSharedMemorySize, SMEM_MT4);

    // launch order keeps the first qkv GEMM at launch #6 for ncu (-s 5 -c 1)
    embed_kernel<<<(MROW * EMB + 255) / 256, 256>>>(x_idx, wte, wpe, gx);          // 1
    cvtT2_kernel<<<dim3(96, 12, 2 * NLAYER), 256>>>(                               // 2
        attn_w, wq, EMB, 3 * EMB, fc1_w, w1, EMB, 4 * EMB);
    cvtT2_kernel<<<dim3(24, 48, 2 * NLAYER), 256>>>(                               // 3
        proj_w, wp, EMB, EMB, fc2_w, w2, 4 * EMB, EMB);
    cvt_kernel<<<(VOCAB * EMB / 4 + 255) / 256, 256>>>(wte, wt, VOCAB * EMB / 4);  // 4

    for (int l = 0; l < NLAYER; l++) {
        ln_kernel<<<MROW, 256>>>(gx, ln1_w + (size_t)l * EMB, ln1_b + (size_t)l * EMB, gh);  // 5

        // qkv = h @ attn_w + attn_b -> fp16  (N=2304, 128x128 tiles)              // 6 <- ncu
        tc_gemm<5, 0, 4><<<32 * 18, 128, SMEM_MT4>>>(
            gh, wq + (size_t)l * 3 * EMB * EMB,
            attn_b + (size_t)l * 3 * EMB, nullptr, nullptr, gqkv, 3 * EMB, EMB);

        fattn_kernel<<<dim3(BATCH * NHEAD, TLEN / 64), 128>>>(gqkv, gy);

        // x = x + y @ proj_w + proj_b  (N=768, 64x128 tiles -> 384 CTAs)
        tc_gemm<2, 0, 2><<<64 * 6, 128, SMEM_MT2>>>(
            gy, wp + (size_t)l * EMB * EMB,
            proj_b + (size_t)l * EMB, gx, gx, nullptr, EMB, EMB);

        ln_kernel<<<MROW, 256>>>(gx, ln2_w + (size_t)l * EMB, ln2_b + (size_t)l * EMB, gh);

        // f1 = gelu(h @ fc1_w + fc1_b) -> fp16  (N=3072, 128x128 tiles)
        tc_gemm<3, 0, 4><<<32 * 24, 128, SMEM_MT4>>>(
            gh, w1 + (size_t)l * 4 * EMB * EMB,
            fc1_b + (size_t)l * 4 * EMB, nullptr, nullptr, gf1, 4 * EMB, EMB);

        // x = x + f1 @ fc2_w + fc2_b   (N=768, K=3072, 64x128 tiles -> 384 CTAs)
        tc_gemm<2, 0, 2><<<64 * 6, 128, SMEM_MT2>>>(
            gf1, w2 + (size_t)l * 4 * EMB * EMB,
            fc2_b + (size_t)l * EMB, gx, gx, nullptr, EMB, 4 * EMB);
    }

    ln_kernel<<<MROW, 256>>>(gx, lnf_w, lnf_b, gh);

    // logits = h @ wte^T  (N=50257, 128x128 tiles, ragged)
    tc_gemm<0, 1, 4><<<32 * 393, 128, SMEM_MT4>>>(
        gh, wt, nullptr, nullptr, out, nullptr, VOCAB, EMB);
}